// round 9
// baseline (speedup 1.0000x reference)
#include <cuda_runtime.h>
#include <cuda_fp16.h>
#include <mma.h>
#include <math.h>
#include <stdint.h>

using namespace nvcuda;

#define B_DIM 1024
#define D_DIM 256
#define NPAD  100352
#define NSPLIT 37
#define NT1 392            // NPAD / 256

__device__ __half g_projh[B_DIM * D_DIM];
__device__ float g_bias[NPAD];
__device__ float g_z[(size_t)B_DIM * NPAD];
__device__ float g_L[B_DIM];
__device__ float g_pm[(size_t)NT1 * B_DIM];
__device__ float g_ps[(size_t)NT1 * B_DIM];
__device__ __half g_patf[(size_t)NPAD * D_DIM];
__device__ float g_part[(size_t)NSPLIT * B_DIM * D_DIM];
__device__ unsigned g_cmax[NPAD];
__device__ int g_logdmax;

// fast exp on FMA pipe (rel err ~3e-6)
__device__ __forceinline__ float fexp(float x) {
    float y = fmaxf(x * 1.44269504088896f, -126.0f);
    float k = rintf(y);
    float f = y - k;
    float p = 1.3333558146e-3f;
    p = fmaf(p, f, 9.6181291076e-3f);
    p = fmaf(p, f, 5.5504108664e-2f);
    p = fmaf(p, f, 2.4022650696e-1f);
    p = fmaf(p, f, 6.9314718056e-1f);
    p = fmaf(p, f, 1.0f);
    return p * __int_as_float(((int)k + 127) << 23);
}
__device__ __forceinline__ uint32_t pk2h(float lo, float hi) {
    uint32_t d; asm("cvt.rn.f16x2.f32 %0, %1, %2;" : "=r"(d) : "f"(hi), "f"(lo)); return d;
}
__device__ __forceinline__ uint32_t smem_u32(const void* p) {
    uint32_t a;
    asm("{ .reg .u64 t; cvta.to.shared.u64 t, %1; cvt.u32.u64 %0, t; }" : "=r"(a) : "l"(p));
    return a;
}
#define CP16(dst, src) \
    asm volatile("cp.async.cg.shared.global [%0], [%1], 16;" :: "r"(dst), "l"(src))
#define CP_COMMIT() asm volatile("cp.async.commit_group;" ::: "memory")
#define CP_WAIT0()  asm volatile("cp.async.wait_group 0;" ::: "memory")

// -------------------- prep ----------------------------------------------------
__global__ void init_kernel(int Nn) {
    int i = blockIdx.x * blockDim.x + threadIdx.x;
    if (i < Nn) g_cmax[i] = 0u;
    if (i == 0) g_logdmax = 0;
}

__global__ void proj_kernel(const float* __restrict__ state, const float* __restrict__ W) {
    __shared__ float s[D_DIM];
    int b = blockIdx.x, j = threadIdx.x;
    s[j] = state[b * D_DIM + j];
    __syncthreads();
    const float* wr = W + j * D_DIM;
    float acc = 0.f;
#pragma unroll 16
    for (int d = 0; d < D_DIM; ++d) acc = fmaf(s[d], wr[d], acc);
    g_projh[b * D_DIM + j] = __float2half_rn(acc);
}

__global__ void bias_kernel(const float* __restrict__ depths,
                            const float* __restrict__ gate, int Nn) {
    int i = blockIdx.x * 256 + threadIdx.x;
    float lv = 0.f;
    if (i < Nn) {
        float d = depths[i], g = gate[i];
        g_bias[i] = logf(fmaxf(d, 1e-8f)) + logf(fmaxf(g, 1e-8f));
        lv = log1pf(d);
    }
    __shared__ float red[256];
    red[threadIdx.x] = lv;
    __syncthreads();
#pragma unroll
    for (int o = 128; o > 0; o >>= 1) {
        if (threadIdx.x < o) red[threadIdx.x] = fmaxf(red[threadIdx.x], red[threadIdx.x + o]);
        __syncthreads();
    }
    if (threadIdx.x == 0) atomicMax(&g_logdmax, __float_as_int(red[0]));
}

__global__ void patprep_kernel(const float* __restrict__ pat, int Nn) {
    long i = (long)blockIdx.x * 256 + threadIdx.x;
    long e0 = i * 4;
    long n = e0 >> 8;
    float4 v = (n < Nn) ? *(const float4*)&pat[e0] : make_float4(0.f, 0.f, 0.f, 0.f);
    *(uint2*)&g_patf[e0] = make_uint2(pk2h(v.x, v.y), pk2h(v.z, v.w));
}

// -------------------- gemm1: z = proj @ pat^T + bias (fp16, 64x64 warp tile) --
// CTA tile 128(M) x 256(N), 8 warps (2x4 of 64x64), k-chunks 32, double buffer.
// smem/stage: A[128][40] 10240 + B[256][40] 20480 = 30720; x2 = 61440
// epilogue overlay: float Cs[128][264] = 135168
#define SM1_BYTES 135168
__global__ __launch_bounds__(256) void gemm1_kernel(int Nn) {
    extern __shared__ char sm[];
    const uint32_t sb = smem_u32(sm);
    float* Cs = (float*)sm;
    const int tid = threadIdx.x, wid = tid >> 5;
    const int wm = wid >> 2, wn = wid & 3;              // 2 x 4 warps, tile 64 x 64
    const int m0 = blockIdx.x * 128;
    const long n0 = (long)blockIdx.y * 256;

    wmma::fragment<wmma::accumulator, 16, 16, 16, float> acc[4][4];
#pragma unroll
    for (int mi = 0; mi < 4; ++mi)
#pragma unroll
        for (int ni = 0; ni < 4; ++ni) wmma::fill_fragment(acc[mi][ni], 0.0f);

    const int ar = tid >> 1, ab = (tid & 1) * 32;       // A: 32B per thread
    const char* sA = (const char*)(g_projh + (size_t)(m0 + ar) * D_DIM) + ab;
    const char* sB = (const char*)(g_patf + (n0 + tid) * D_DIM);
    const uint32_t dA = sb + ar * 80 + ab;
    const uint32_t dB = sb + 10240 + tid * 80;

#define G1_ISSUE(c, buf) do { \
        long ob = (long)(c) * 64; \
        uint32_t da = dA + (buf) * 30720, db = dB + (buf) * 30720; \
        CP16(da, sA + ob); CP16(da + 16, sA + ob + 16); \
        CP16(db, sB + ob); CP16(db + 16, sB + ob + 16); \
        CP16(db + 32, sB + ob + 32); CP16(db + 48, sB + ob + 48); \
        CP_COMMIT(); } while (0)

    G1_ISSUE(0, 0);
    CP_WAIT0();
    __syncthreads();

    for (int c = 0; c < 8; ++c) {
        const int cur = c & 1;
        if (c < 7) G1_ISSUE(c + 1, cur ^ 1);
        const __half* Ah = (const __half*)(sm + cur * 30720);
        const __half* Bs = (const __half*)(sm + cur * 30720 + 10240);
#pragma unroll
        for (int kk = 0; kk < 32; kk += 16) {
            wmma::fragment<wmma::matrix_a, 16, 16, 16, __half, wmma::row_major> ah[4];
            wmma::fragment<wmma::matrix_b, 16, 16, 16, __half, wmma::col_major> bh[4];
#pragma unroll
            for (int mi = 0; mi < 4; ++mi)
                wmma::load_matrix_sync(ah[mi], &Ah[(wm * 64 + mi * 16) * 40 + kk], 40);
#pragma unroll
            for (int ni = 0; ni < 4; ++ni)
                wmma::load_matrix_sync(bh[ni], &Bs[(wn * 64 + ni * 16) * 40 + kk], 40);
#pragma unroll
            for (int mi = 0; mi < 4; ++mi)
#pragma unroll
                for (int ni = 0; ni < 4; ++ni)
                    wmma::mma_sync(acc[mi][ni], ah[mi], bh[ni], acc[mi][ni]);
        }
        if (c < 7) CP_WAIT0();
        __syncthreads();
    }

#pragma unroll
    for (int mi = 0; mi < 4; ++mi)
#pragma unroll
        for (int ni = 0; ni < 4; ++ni)
            wmma::store_matrix_sync(&Cs[(wm * 64 + mi * 16) * 264 + wn * 64 + ni * 16],
                                    acc[mi][ni], 264, wmma::mem_row_major);
    __syncthreads();

    // epilogue: add bias, write z, per-tile row max + sum(exp)
    const int r2 = tid >> 1, hc = (tid & 1) * 128;
    const int m = m0 + r2;
    float* zrow = g_z + (size_t)m * NPAD;
    const float* crow = Cs + r2 * 264 + hc;
    float vmax = -3.0e38f;
#pragma unroll
    for (int j = 0; j < 128; j += 4) {
        long n = n0 + hc + j;
        if (n + 4 <= Nn) {
            float4 b4 = *(const float4*)&g_bias[n];
            float4 c4 = *(const float4*)&crow[j];
            float4 o = make_float4(c4.x + b4.x, c4.y + b4.y, c4.z + b4.z, c4.w + b4.w);
            vmax = fmaxf(vmax, fmaxf(fmaxf(o.x, o.y), fmaxf(o.z, o.w)));
            *(float4*)&zrow[n] = o;
        } else {
            for (int q = 0; q < 4; ++q)
                if (n + q < Nn) {
                    float v = crow[j + q] + g_bias[n + q];
                    vmax = fmaxf(vmax, v);
                    zrow[n + q] = v;
                }
        }
    }
    float pmv = fmaxf(vmax, __shfl_xor_sync(0xffffffffu, vmax, 1));
    float s = 0.f;
#pragma unroll
    for (int j = 0; j < 128; j += 4) {
        long n = n0 + hc + j;
        if (n + 4 <= Nn) {
            float4 b4 = *(const float4*)&g_bias[n];
            float4 c4 = *(const float4*)&crow[j];
            s += fexp(c4.x + b4.x - pmv) + fexp(c4.y + b4.y - pmv)
               + fexp(c4.z + b4.z - pmv) + fexp(c4.w + b4.w - pmv);
        } else {
            for (int q = 0; q < 4; ++q)
                if (n + q < Nn) s += fexp(crow[j + q] + g_bias[n + q] - pmv);
        }
    }
    s += __shfl_xor_sync(0xffffffffu, s, 1);
    if ((tid & 1) == 0) {
        g_pm[(size_t)blockIdx.y * B_DIM + m] = pmv;
        g_ps[(size_t)blockIdx.y * B_DIM + m] = s;
    }
}

// -------------------- lse merge -------------------------------------------------
__global__ void lse_merge_kernel(int ntiles) {
    int m = blockIdx.x * 256 + threadIdx.x;
    if (m >= B_DIM) return;
    float M = -3.0e38f;
    for (int t = 0; t < ntiles; ++t) M = fmaxf(M, g_pm[(size_t)t * B_DIM + m]);
    float S = 0.f;
    for (int t = 0; t < ntiles; ++t) {
        float pm = g_pm[(size_t)t * B_DIM + m];
        if (pm > -1.0e38f) S += g_ps[(size_t)t * B_DIM + m] * fexp(pm - M);
    }
    g_L[m] = M + logf(S);
}

// -------------------- gemm2: part = exp(z-L) @ pat + colmax (64x64 warp tile) --
// smem/stage: A[128][40] 10240 + B[32][264] 16896 = 27136; x2 = 54272
// epilogue overlay: float Cs[128][264] = 135168
#define SM2_BYTES 135168
__global__ __launch_bounds__(256) void gemm2_kernel(int Nn, int CHv) {
    extern __shared__ char sm[];
    const uint32_t sb = smem_u32(sm);
    float* Cs = (float*)sm;
    __shared__ unsigned scm[2][32];
    const int tid = threadIdx.x, wid = tid >> 5, lane = tid & 31;
    const int wm = wid >> 2, wd = wid & 3;              // 2 x 4 warps, tile 64 x 64
    const int m0 = blockIdx.x * 128;
    const int sp = blockIdx.y;
    const int ns = sp * CHv, ne = min(ns + CHv, Nn);
    if (ns >= ne) {
        const size_t pb = ((size_t)sp * B_DIM + m0) * D_DIM;
        for (int i = tid; i < 128 * D_DIM / 4; i += 256)
            *(float4*)&g_part[pb + (size_t)i * 4] = make_float4(0.f, 0.f, 0.f, 0.f);
        return;
    }
    const int nch = (ne - ns + 31) / 32;

    wmma::fragment<wmma::accumulator, 16, 16, 16, float> acc[4][4];
#pragma unroll
    for (int mi = 0; mi < 4; ++mi)
#pragma unroll
        for (int ni = 0; ni < 4; ++ni) wmma::fill_fragment(acc[mi][ni], 0.0f);

    const int r = tid >> 1, ng = (tid & 1) * 16;
    const float Lm = g_L[m0 + r];
    const float* zrow = g_z + (size_t)(m0 + r) * NPAD;
    const uint32_t dA = sb + r * 80 + ng * 2;
    if (tid < 32) { scm[0][tid] = 0u; scm[1][tid] = 0u; }
    __syncthreads();

    float zv[16];

    // load z for a chunk into registers (prefetch; garbage -> -1e30 so exp ~ 0)
#define G2_ZLOAD(k0v) do { \
        long nbase = (long)(k0v) + ng; \
        if (nbase + 16 <= Nn) { \
            *(float4*)&zv[0]  = *(const float4*)&zrow[nbase]; \
            *(float4*)&zv[4]  = *(const float4*)&zrow[nbase + 4]; \
            *(float4*)&zv[8]  = *(const float4*)&zrow[nbase + 8]; \
            *(float4*)&zv[12] = *(const float4*)&zrow[nbase + 12]; \
        } else { \
            for (int j = 0; j < 16; ++j) { \
                long nn = nbase + j; \
                zv[j] = (nn < Nn) ? zrow[nn] : -1.0e30f; \
            } \
        } } while (0)

    // exp + pack + store to A smem + colmax
#define G2_WSTORE(buf, chpar) do { \
        float e[16]; \
        for (int j = 0; j < 16; ++j) e[j] = fexp(zv[j] - Lm); \
        uint32_t h[8]; \
        for (int j = 0; j < 8; ++j) h[j] = pk2h(e[2 * j], e[2 * j + 1]); \
        uint32_t doff = dA + (buf) * 27136 - sb; \
        *(uint4*)(sm + doff) = make_uint4(h[0], h[1], h[2], h[3]); \
        *(uint4*)(sm + doff + 16) = make_uint4(h[4], h[5], h[6], h[7]); \
        uint32_t cm[16]; \
        for (int j = 0; j < 16; ++j) cm[j] = __float_as_uint(e[j]); \
        for (int off = 2; off <= 16; off <<= 1) \
            for (int j = 0; j < 16; ++j) { \
                uint32_t o = __shfl_xor_sync(0xffffffffu, cm[j], off); \
                cm[j] = (o > cm[j]) ? o : cm[j]; \
            } \
        if (lane < 2) \
            for (int j = 0; j < 16; ++j) atomicMax(&scm[chpar][lane * 16 + j], cm[j]); \
    } while (0)

#define G2_BISSUE(k0v, buf) do { \
        uint32_t base = sb + (buf) * 27136 + 10240; \
        const char* psrc = (const char*)(g_patf + (size_t)(k0v) * D_DIM); \
        for (int k = 0; k < 4; ++k) { \
            int s0 = tid + k * 256; \
            CP16(base + (s0 >> 5) * 528 + (s0 & 31) * 16, psrc + (s0 >> 5) * 512 + (s0 & 31) * 16); \
        } \
        CP_COMMIT(); } while (0)

    G2_BISSUE(ns, 0);
    G2_ZLOAD(ns);
    G2_WSTORE(0, 0);
    CP_WAIT0();
    __syncthreads();

    for (int ci = 0; ci < nch; ++ci) {
        const int cur = ci & 1;
        if (ci > 0 && tid < 32) {
            int n = ns + (ci - 1) * 32 + tid;
            unsigned v = scm[cur ^ 1][tid];
            if (n < Nn && v) atomicMax(&g_cmax[n], v);
            scm[cur ^ 1][tid] = 0u;
        }
        const bool pre = (ci + 1 < nch);
        if (pre) {
            G2_BISSUE(ns + (ci + 1) * 32, cur ^ 1);
            G2_ZLOAD(ns + (ci + 1) * 32);       // prefetch z under MMA
        }

        const __half* Ah = (const __half*)(sm + cur * 27136);
        const __half* Bs = (const __half*)(sm + cur * 27136 + 10240);
#pragma unroll
        for (int kk = 0; kk < 32; kk += 16) {
            wmma::fragment<wmma::matrix_a, 16, 16, 16, __half, wmma::row_major> ah[4];
            wmma::fragment<wmma::matrix_b, 16, 16, 16, __half, wmma::row_major> bh[4];
#pragma unroll
            for (int mi = 0; mi < 4; ++mi)
                wmma::load_matrix_sync(ah[mi], &Ah[(wm * 64 + mi * 16) * 40 + kk], 40);
#pragma unroll
            for (int ni = 0; ni < 4; ++ni)
                wmma::load_matrix_sync(bh[ni], &Bs[kk * 264 + wd * 64 + ni * 16], 264);
#pragma unroll
            for (int mi = 0; mi < 4; ++mi)
#pragma unroll
                for (int ni = 0; ni < 4; ++ni)
                    wmma::mma_sync(acc[mi][ni], ah[mi], bh[ni], acc[mi][ni]);
        }
        if (pre) {
            G2_WSTORE(cur ^ 1, cur ^ 1);
            CP_WAIT0();
        }
        __syncthreads();
    }
    if (tid < 32) {
        int n = ns + (nch - 1) * 32 + tid;
        unsigned v = scm[(nch - 1) & 1][tid];
        if (n < Nn && v) atomicMax(&g_cmax[n], v);
    }

#pragma unroll
    for (int mi = 0; mi < 4; ++mi)
#pragma unroll
        for (int ni = 0; ni < 4; ++ni)
            wmma::store_matrix_sync(&Cs[(wm * 64 + mi * 16) * 264 + wd * 64 + ni * 16],
                                    acc[mi][ni], 264, wmma::mem_row_major);
    __syncthreads();
    const int rr = tid >> 1, cgr = (tid & 1) * 128;
    const size_t ob = ((size_t)sp * B_DIM + m0 + rr) * D_DIM + cgr;
#pragma unroll
    for (int j = 0; j < 128; j += 4)
        *(float4*)&g_part[ob + j] = *(const float4*)&Cs[rr * 264 + cgr + j];
}

// -------------------- reductions / output --------------------------------------
__global__ void reduce_ret_kernel(float* __restrict__ out) {
    size_t i = (size_t)blockIdx.x * 256 + threadIdx.x;
    float4 s = make_float4(0.f, 0.f, 0.f, 0.f);
    for (int sp = 0; sp < NSPLIT; ++sp) {
        float4 v = *(const float4*)&g_part[(size_t)sp * (B_DIM * D_DIM) + i * 4];
        s.x += v.x; s.y += v.y; s.z += v.z; s.w += v.w;
    }
    *(float4*)&out[i * 4] = s;
}

__global__ void depths_kernel(const float* __restrict__ depths,
                              float* __restrict__ out, int Nn) {
    int i = blockIdx.x * 256 + threadIdx.x;
    if (i >= Nn) return;
    float d = depths[i];
    float maxw = __uint_as_float(g_cmax[i]);
    float dom = log1pf(d) / fmaxf(__int_as_float(g_logdmax), 1e-8f);
    float rate = 0.01f * (1.0f - 0.7f * dom);
    out[B_DIM * D_DIM + i] = d + ((maxw > 0.1f) ? rate * maxw : 0.0f);
}

extern "C" void kernel_launch(void* const* d_in, const int* in_sizes, int n_in,
                              void* d_out, int out_size) {
    const float* state  = (const float*)d_in[0];
    const float* W      = (const float*)d_in[1];
    const float* pat    = (const float*)d_in[2];
    const float* depths = (const float*)d_in[3];
    const float* gate   = (const float*)d_in[4];
    float* out = (float*)d_out;
    const int Nn = in_sizes[3];

    cudaFuncSetAttribute(gemm1_kernel, cudaFuncAttributeMaxDynamicSharedMemorySize, SM1_BYTES);
    cudaFuncSetAttribute(gemm2_kernel, cudaFuncAttributeMaxDynamicSharedMemorySize, SM2_BYTES);

    const int nbN = (Nn + 255) / 256;
    init_kernel<<<nbN, 256>>>(Nn);
    proj_kernel<<<B_DIM, 256>>>(state, W);
    bias_kernel<<<nbN, 256>>>(depths, gate, Nn);
    patprep_kernel<<<(NPAD * D_DIM / 4) / 256, 256>>>(pat, Nn);

    gemm1_kernel<<<dim3(B_DIM / 128, NT1), 256, SM1_BYTES>>>(Nn);
    lse_merge_kernel<<<B_DIM / 256, 256>>>(NT1);

    const int CHv = ((Nn + NSPLIT * 32 - 1) / (NSPLIT * 32)) * 32;
    gemm2_kernel<<<dim3(B_DIM / 128, NSPLIT), 256, SM2_BYTES>>>(Nn, CHv);

    reduce_ret_kernel<<<(B_DIM * D_DIM / 4) / 256, 256>>>(out);
    depths_kernel<<<nbN, 256>>>(depths, out, Nn);
}

// round 10
// speedup vs baseline: 1.0928x; 1.0928x over previous
#include <cuda_runtime.h>
#include <cuda_fp16.h>
#include <mma.h>
#include <math.h>
#include <stdint.h>

using namespace nvcuda;

#define B_DIM 1024
#define D_DIM 256
#define NPAD  100352
#define NSPLIT 37
#define NT1 392            // NPAD / 256

__device__ __half g_projh[B_DIM * D_DIM];
__device__ float g_bias[NPAD];
__device__ float g_z[(size_t)B_DIM * NPAD];
__device__ float g_L[B_DIM];
__device__ float g_pm[(size_t)NT1 * B_DIM];
__device__ float g_ps[(size_t)NT1 * B_DIM];
__device__ __half g_patf[(size_t)NPAD * D_DIM];
__device__ float g_part[(size_t)NSPLIT * B_DIM * D_DIM];
__device__ unsigned g_cmax[NPAD];
__device__ int g_logdmax;

// fast exp on FMA pipe (rel err ~3e-6)
__device__ __forceinline__ float fexp(float x) {
    float y = fmaxf(x * 1.44269504088896f, -126.0f);
    float k = rintf(y);
    float f = y - k;
    float p = 1.3333558146e-3f;
    p = fmaf(p, f, 9.6181291076e-3f);
    p = fmaf(p, f, 5.5504108664e-2f);
    p = fmaf(p, f, 2.4022650696e-1f);
    p = fmaf(p, f, 6.9314718056e-1f);
    p = fmaf(p, f, 1.0f);
    return p * __int_as_float(((int)k + 127) << 23);
}
__device__ __forceinline__ uint32_t pk2h(float lo, float hi) {
    uint32_t d; asm("cvt.rn.f16x2.f32 %0, %1, %2;" : "=r"(d) : "f"(hi), "f"(lo)); return d;
}
__device__ __forceinline__ uint32_t smem_u32(const void* p) {
    uint32_t a;
    asm("{ .reg .u64 t; cvta.to.shared.u64 t, %1; cvt.u32.u64 %0, t; }" : "=r"(a) : "l"(p));
    return a;
}
#define CP16(dst, src) \
    asm volatile("cp.async.cg.shared.global [%0], [%1], 16;" :: "r"(dst), "l"(src))
#define CP_COMMIT() asm volatile("cp.async.commit_group;" ::: "memory")
#define CP_WAIT0()  asm volatile("cp.async.wait_group 0;" ::: "memory")

// -------------------- prep ----------------------------------------------------
__global__ void init_kernel(int Nn) {
    int i = blockIdx.x * blockDim.x + threadIdx.x;
    if (i < Nn) g_cmax[i] = 0u;
    if (i == 0) g_logdmax = 0;
}

__global__ void proj_kernel(const float* __restrict__ state, const float* __restrict__ W) {
    __shared__ float s[D_DIM];
    int b = blockIdx.x, j = threadIdx.x;
    s[j] = state[b * D_DIM + j];
    __syncthreads();
    const float* wr = W + j * D_DIM;
    float acc = 0.f;
#pragma unroll 16
    for (int d = 0; d < D_DIM; ++d) acc = fmaf(s[d], wr[d], acc);
    g_projh[b * D_DIM + j] = __float2half_rn(acc);
}

__global__ void bias_kernel(const float* __restrict__ depths,
                            const float* __restrict__ gate, int Nn) {
    int i = blockIdx.x * 256 + threadIdx.x;
    float lv = 0.f;
    if (i < Nn) {
        float d = depths[i], g = gate[i];
        g_bias[i] = logf(fmaxf(d, 1e-8f)) + logf(fmaxf(g, 1e-8f));
        lv = log1pf(d);
    }
    __shared__ float red[256];
    red[threadIdx.x] = lv;
    __syncthreads();
#pragma unroll
    for (int o = 128; o > 0; o >>= 1) {
        if (threadIdx.x < o) red[threadIdx.x] = fmaxf(red[threadIdx.x], red[threadIdx.x + o]);
        __syncthreads();
    }
    if (threadIdx.x == 0) atomicMax(&g_logdmax, __float_as_int(red[0]));
}

__global__ void patprep_kernel(const float* __restrict__ pat, int Nn) {
    long i = (long)blockIdx.x * 256 + threadIdx.x;
    long e0 = i * 4;
    long n = e0 >> 8;
    float4 v = (n < Nn) ? *(const float4*)&pat[e0] : make_float4(0.f, 0.f, 0.f, 0.f);
    *(uint2*)&g_patf[e0] = make_uint2(pk2h(v.x, v.y), pk2h(v.z, v.w));
}

// -------------------- gemm1: z = proj @ pat^T + bias (fp16, k-chunk 64) -------
// CTA tile 128(M) x 256(N), 16 warps (4x4 of 32x64), k-chunks 64, double buffer.
// smem/stage: A[128][72]h 18432 + B[256][72]h 36864 = 55296; x2 = 110592
// epilogue overlay: float Cs[128][264] = 135168
#define SM1_BYTES 135168
#define G1_STAGE 55296
__global__ __launch_bounds__(512) void gemm1_kernel(int Nn) {
    extern __shared__ char sm[];
    const uint32_t sb = smem_u32(sm);
    float* Cs = (float*)sm;
    const int tid = threadIdx.x, wid = tid >> 5;
    const int wm = wid >> 2, wn = wid & 3;              // 4 x 4 warps, tile 32 x 64
    const int m0 = blockIdx.x * 128;
    const long n0 = (long)blockIdx.y * 256;

    wmma::fragment<wmma::accumulator, 16, 16, 16, float> acc[2][4];
#pragma unroll
    for (int mi = 0; mi < 2; ++mi)
#pragma unroll
        for (int ni = 0; ni < 4; ++ni) wmma::fill_fragment(acc[mi][ni], 0.0f);

    const int ar = tid >> 2, ac = (tid & 3) * 16;       // A: 32B per thread
    const int br = tid >> 1, bc = (tid & 1) * 32;       // B: 64B per thread
    const char* sA = (const char*)(g_projh + (size_t)(m0 + ar) * D_DIM + ac);
    const char* sB = (const char*)(g_patf + (n0 + br) * D_DIM + bc);
    const uint32_t dA = sb + ar * 144 + ac * 2;
    const uint32_t dB = sb + 18432 + br * 144 + bc * 2;

#define G1_ISSUE(c, buf) do { \
        long ob = (long)(c) * 128; \
        uint32_t da = dA + (buf) * G1_STAGE, db = dB + (buf) * G1_STAGE; \
        CP16(da, sA + ob); CP16(da + 16, sA + ob + 16); \
        CP16(db, sB + ob); CP16(db + 16, sB + ob + 16); \
        CP16(db + 32, sB + ob + 32); CP16(db + 48, sB + ob + 48); \
        CP_COMMIT(); } while (0)

    G1_ISSUE(0, 0);
    CP_WAIT0();
    __syncthreads();

    for (int c = 0; c < 4; ++c) {
        const int cur = c & 1;
        if (c < 3) G1_ISSUE(c + 1, cur ^ 1);
        const __half* Ah = (const __half*)(sm + cur * G1_STAGE);
        const __half* Bs = (const __half*)(sm + cur * G1_STAGE + 18432);
#pragma unroll
        for (int kk = 0; kk < 64; kk += 16) {
            wmma::fragment<wmma::matrix_a, 16, 16, 16, __half, wmma::row_major> ah[2];
            wmma::fragment<wmma::matrix_b, 16, 16, 16, __half, wmma::col_major> bh[4];
#pragma unroll
            for (int mi = 0; mi < 2; ++mi)
                wmma::load_matrix_sync(ah[mi], &Ah[(wm * 32 + mi * 16) * 72 + kk], 72);
#pragma unroll
            for (int ni = 0; ni < 4; ++ni)
                wmma::load_matrix_sync(bh[ni], &Bs[(wn * 64 + ni * 16) * 72 + kk], 72);
#pragma unroll
            for (int mi = 0; mi < 2; ++mi)
#pragma unroll
                for (int ni = 0; ni < 4; ++ni)
                    wmma::mma_sync(acc[mi][ni], ah[mi], bh[ni], acc[mi][ni]);
        }
        if (c < 3) CP_WAIT0();
        __syncthreads();
    }

#pragma unroll
    for (int mi = 0; mi < 2; ++mi)
#pragma unroll
        for (int ni = 0; ni < 4; ++ni)
            wmma::store_matrix_sync(&Cs[(wm * 32 + mi * 16) * 264 + wn * 64 + ni * 16],
                                    acc[mi][ni], 264, wmma::mem_row_major);
    __syncthreads();

    // epilogue: add bias, write z, per-tile row max + sum(exp)
    const int r2 = tid >> 2, hc = (tid & 3) * 64;
    const int m = m0 + r2;
    float* zrow = g_z + (size_t)m * NPAD;
    const float* crow = Cs + r2 * 264 + hc;
    float vmax = -3.0e38f;
#pragma unroll
    for (int j = 0; j < 64; j += 4) {
        long n = n0 + hc + j;
        if (n + 4 <= Nn) {
            float4 b4 = *(const float4*)&g_bias[n];
            float4 c4 = *(const float4*)&crow[j];
            float4 o = make_float4(c4.x + b4.x, c4.y + b4.y, c4.z + b4.z, c4.w + b4.w);
            vmax = fmaxf(vmax, fmaxf(fmaxf(o.x, o.y), fmaxf(o.z, o.w)));
            *(float4*)&zrow[n] = o;
        } else {
            for (int q = 0; q < 4; ++q)
                if (n + q < Nn) {
                    float v = crow[j + q] + g_bias[n + q];
                    vmax = fmaxf(vmax, v);
                    zrow[n + q] = v;
                }
        }
    }
    float pmv = fmaxf(vmax, __shfl_xor_sync(0xffffffffu, vmax, 1));
    pmv = fmaxf(pmv, __shfl_xor_sync(0xffffffffu, pmv, 2));
    float s = 0.f;
#pragma unroll
    for (int j = 0; j < 64; j += 4) {
        long n = n0 + hc + j;
        if (n + 4 <= Nn) {
            float4 b4 = *(const float4*)&g_bias[n];
            float4 c4 = *(const float4*)&crow[j];
            s += fexp(c4.x + b4.x - pmv) + fexp(c4.y + b4.y - pmv)
               + fexp(c4.z + b4.z - pmv) + fexp(c4.w + b4.w - pmv);
        } else {
            for (int q = 0; q < 4; ++q)
                if (n + q < Nn) s += fexp(crow[j + q] + g_bias[n + q] - pmv);
        }
    }
    s += __shfl_xor_sync(0xffffffffu, s, 1);
    s += __shfl_xor_sync(0xffffffffu, s, 2);
    if ((tid & 3) == 0) {
        g_pm[(size_t)blockIdx.y * B_DIM + m] = pmv;
        g_ps[(size_t)blockIdx.y * B_DIM + m] = s;
    }
}

// -------------------- lse merge -------------------------------------------------
__global__ void lse_merge_kernel(int ntiles) {
    int m = blockIdx.x * 256 + threadIdx.x;
    if (m >= B_DIM) return;
    float M = -3.0e38f;
    for (int t = 0; t < ntiles; ++t) M = fmaxf(M, g_pm[(size_t)t * B_DIM + m]);
    float S = 0.f;
    for (int t = 0; t < ntiles; ++t) {
        float pm = g_pm[(size_t)t * B_DIM + m];
        if (pm > -1.0e38f) S += g_ps[(size_t)t * B_DIM + m] * fexp(pm - M);
    }
    g_L[m] = M + logf(S);
}

// -------------------- gemm2: part = exp(z-L) @ pat + colmax (k-chunk 64) -------
// smem/stage: A[128][72]h 18432 + B[64][264]h 33792 = 52224; x2 = 104448
// epilogue overlay: float Cs[128][264] = 135168
#define SM2_BYTES 135168
#define G2_STAGE 52224
__global__ __launch_bounds__(512) void gemm2_kernel(int Nn, int CHv) {
    extern __shared__ char sm[];
    const uint32_t sb = smem_u32(sm);
    float* Cs = (float*)sm;
    __shared__ unsigned scm[2][64];
    const int tid = threadIdx.x, wid = tid >> 5, lane = tid & 31;
    const int wm = wid >> 2, wd = wid & 3;              // 4 x 4 warps, tile 32 x 64
    const int m0 = blockIdx.x * 128;
    const int sp = blockIdx.y;
    const int ns = sp * CHv, ne = min(ns + CHv, Nn);
    if (ns >= ne) {
        const size_t pb = ((size_t)sp * B_DIM + m0) * D_DIM;
        for (int i = tid; i < 128 * D_DIM / 4; i += 512)
            *(float4*)&g_part[pb + (size_t)i * 4] = make_float4(0.f, 0.f, 0.f, 0.f);
        return;
    }
    const int nch = (ne - ns + 63) / 64;

    wmma::fragment<wmma::accumulator, 16, 16, 16, float> acc[2][4];
#pragma unroll
    for (int mi = 0; mi < 2; ++mi)
#pragma unroll
        for (int ni = 0; ni < 4; ++ni) wmma::fill_fragment(acc[mi][ni], 0.0f);

    const int r = tid >> 2, ng = (tid & 3) * 16;
    const float Lm = g_L[m0 + r];
    const float* zrow = g_z + (size_t)(m0 + r) * NPAD;
    const uint32_t dA = sb + r * 144 + ng * 2;
    if (tid < 64) { scm[0][tid] = 0u; scm[1][tid] = 0u; }
    __syncthreads();

    float zv[16];

    // prefetch z for a chunk into registers (guard -> -1e30 so exp ~ 0)
#define G2_ZLOAD(k0v) do { \
        long nbase = (long)(k0v) + ng; \
        if (nbase + 16 <= Nn) { \
            *(float4*)&zv[0]  = *(const float4*)&zrow[nbase]; \
            *(float4*)&zv[4]  = *(const float4*)&zrow[nbase + 4]; \
            *(float4*)&zv[8]  = *(const float4*)&zrow[nbase + 8]; \
            *(float4*)&zv[12] = *(const float4*)&zrow[nbase + 12]; \
        } else { \
            for (int j = 0; j < 16; ++j) { \
                long nn = nbase + j; \
                zv[j] = (nn < Nn) ? zrow[nn] : -1.0e30f; \
            } \
        } } while (0)

    // exp + pack + store to A smem + colmax into scm[chpar]
#define G2_WSTORE(buf, chpar) do { \
        float e[16]; \
        for (int j = 0; j < 16; ++j) e[j] = fexp(zv[j] - Lm); \
        uint32_t h[8]; \
        for (int j = 0; j < 8; ++j) h[j] = pk2h(e[2 * j], e[2 * j + 1]); \
        uint32_t doff = dA + (buf) * G2_STAGE - sb; \
        *(uint4*)(sm + doff) = make_uint4(h[0], h[1], h[2], h[3]); \
        *(uint4*)(sm + doff + 16) = make_uint4(h[4], h[5], h[6], h[7]); \
        uint32_t cm[16]; \
        for (int j = 0; j < 16; ++j) cm[j] = __float_as_uint(e[j]); \
        for (int off = 4; off <= 16; off <<= 1) \
            for (int j = 0; j < 16; ++j) { \
                uint32_t o = __shfl_xor_sync(0xffffffffu, cm[j], off); \
                cm[j] = (o > cm[j]) ? o : cm[j]; \
            } \
        if (lane < 4) \
            for (int j = 0; j < 16; ++j) atomicMax(&scm[chpar][lane * 16 + j], cm[j]); \
    } while (0)

#define G2_BISSUE(k0v, buf) do { \
        uint32_t base = sb + (buf) * G2_STAGE + 18432; \
        const char* psrc = (const char*)(g_patf + (size_t)(k0v) * D_DIM); \
        for (int k = 0; k < 4; ++k) { \
            int s0 = tid + k * 512; \
            CP16(base + (s0 >> 5) * 528 + (s0 & 31) * 16, psrc + (s0 >> 5) * 512 + (s0 & 31) * 16); \
        } \
        CP_COMMIT(); } while (0)

    G2_BISSUE(ns, 0);
    G2_ZLOAD(ns);
    G2_WSTORE(0, 0);
    CP_WAIT0();
    __syncthreads();

    for (int ci = 0; ci < nch; ++ci) {
        const int cur = ci & 1;
        if (ci > 0 && tid < 64) {
            int n = ns + (ci - 1) * 64 + tid;
            unsigned v = scm[cur ^ 1][tid];
            if (n < Nn && v) atomicMax(&g_cmax[n], v);
            scm[cur ^ 1][tid] = 0u;
        }
        const bool pre = (ci + 1 < nch);
        if (pre) {
            G2_BISSUE(ns + (ci + 1) * 64, cur ^ 1);
            G2_ZLOAD(ns + (ci + 1) * 64);       // prefetch z under MMA
        }

        const __half* Ah = (const __half*)(sm + cur * G2_STAGE);
        const __half* Bs = (const __half*)(sm + cur * G2_STAGE + 18432);
#pragma unroll
        for (int kk = 0; kk < 64; kk += 16) {
            wmma::fragment<wmma::matrix_a, 16, 16, 16, __half, wmma::row_major> ah[2];
            wmma::fragment<wmma::matrix_b, 16, 16, 16, __half, wmma::row_major> bh[4];
#pragma unroll
            for (int mi = 0; mi < 2; ++mi)
                wmma::load_matrix_sync(ah[mi], &Ah[(wm * 32 + mi * 16) * 72 + kk], 72);
#pragma unroll
            for (int ni = 0; ni < 4; ++ni)
                wmma::load_matrix_sync(bh[ni], &Bs[kk * 264 + wd * 64 + ni * 16], 264);
#pragma unroll
            for (int mi = 0; mi < 2; ++mi)
#pragma unroll
                for (int ni = 0; ni < 4; ++ni)
                    wmma::mma_sync(acc[mi][ni], ah[mi], bh[ni], acc[mi][ni]);
        }
        if (pre) {
            G2_WSTORE(cur ^ 1, cur ^ 1);
            CP_WAIT0();
        }
        __syncthreads();
    }
    if (tid < 64) {
        int n = ns + (nch - 1) * 64 + tid;
        unsigned v = scm[(nch - 1) & 1][tid];
        if (n < Nn && v) atomicMax(&g_cmax[n], v);
    }

#pragma unroll
    for (int mi = 0; mi < 2; ++mi)
#pragma unroll
        for (int ni = 0; ni < 4; ++ni)
            wmma::store_matrix_sync(&Cs[(wm * 32 + mi * 16) * 264 + wd * 64 + ni * 16],
                                    acc[mi][ni], 264, wmma::mem_row_major);
    __syncthreads();
    const int rr = tid >> 2, cgr = (tid & 3) * 64;
    const size_t ob = ((size_t)sp * B_DIM + m0 + rr) * D_DIM + cgr;
#pragma unroll
    for (int j = 0; j < 64; j += 4)
        *(float4*)&g_part[ob + j] = *(const float4*)&Cs[rr * 264 + cgr + j];
}

// -------------------- reductions / output --------------------------------------
__global__ void reduce_ret_kernel(float* __restrict__ out) {
    size_t i = (size_t)blockIdx.x * 256 + threadIdx.x;
    float4 s = make_float4(0.f, 0.f, 0.f, 0.f);
    for (int sp = 0; sp < NSPLIT; ++sp) {
        float4 v = *(const float4*)&g_part[(size_t)sp * (B_DIM * D_DIM) + i * 4];
        s.x += v.x; s.y += v.y; s.z += v.z; s.w += v.w;
    }
    *(float4*)&out[i * 4] = s;
}

__global__ void depths_kernel(const float* __restrict__ depths,
                              float* __restrict__ out, int Nn) {
    int i = blockIdx.x * 256 + threadIdx.x;
    if (i >= Nn) return;
    float d = depths[i];
    float maxw = __uint_as_float(g_cmax[i]);
    float dom = log1pf(d) / fmaxf(__int_as_float(g_logdmax), 1e-8f);
    float rate = 0.01f * (1.0f - 0.7f * dom);
    out[B_DIM * D_DIM + i] = d + ((maxw > 0.1f) ? rate * maxw : 0.0f);
}

extern "C" void kernel_launch(void* const* d_in, const int* in_sizes, int n_in,
                              void* d_out, int out_size) {
    const float* state  = (const float*)d_in[0];
    const float* W      = (const float*)d_in[1];
    const float* pat    = (const float*)d_in[2];
    const float* depths = (const float*)d_in[3];
    const float* gate   = (const float*)d_in[4];
    float* out = (float*)d_out;
    const int Nn = in_sizes[3];

    cudaFuncSetAttribute(gemm1_kernel, cudaFuncAttributeMaxDynamicSharedMemorySize, SM1_BYTES);
    cudaFuncSetAttribute(gemm2_kernel, cudaFuncAttributeMaxDynamicSharedMemorySize, SM2_BYTES);

    const int nbN = (Nn + 255) / 256;
    init_kernel<<<nbN, 256>>>(Nn);
    proj_kernel<<<B_DIM, 256>>>(state, W);
    bias_kernel<<<nbN, 256>>>(depths, gate, Nn);
    patprep_kernel<<<(NPAD * D_DIM / 4) / 256, 256>>>(pat, Nn);

    gemm1_kernel<<<dim3(B_DIM / 128, NT1), 512, SM1_BYTES>>>(Nn);
    lse_merge_kernel<<<B_DIM / 256, 256>>>(NT1);

    const int CHv = ((Nn + NSPLIT * 64 - 1) / (NSPLIT * 64)) * 64;
    gemm2_kernel<<<dim3(B_DIM / 128, NSPLIT), 512, SM2_BYTES>>>(Nn, CHv);

    reduce_ret_kernel<<<(B_DIM * D_DIM / 4) / 256, 256>>>(out);
    depths_kernel<<<nbN, 256>>>(depths, out, Nn);
}

// round 11
// speedup vs baseline: 1.2080x; 1.1054x over previous
#include <cuda_runtime.h>
#include <cuda_fp16.h>
#include <mma.h>
#include <math.h>
#include <stdint.h>

using namespace nvcuda;

#define B_DIM 1024
#define D_DIM 256
#define NPAD  100352
#define NSPLIT 37
#define NT1 392            // NPAD / 256

__device__ __half g_projh[B_DIM * D_DIM];
__device__ float g_bias[NPAD];
__device__ __half g_e16[(size_t)B_DIM * NPAD];   // exp(z - pm_tile), fp16
__device__ float g_L[B_DIM];
__device__ float g_pm[(size_t)NT1 * B_DIM];
__device__ float g_ps[(size_t)NT1 * B_DIM];
__device__ __half g_patf[(size_t)NPAD * D_DIM];
__device__ float g_part[(size_t)NSPLIT * B_DIM * D_DIM];
__device__ unsigned g_cmax[NPAD];
__device__ int g_logdmax;

// fast exp on FMA pipe (rel err ~3e-6)
__device__ __forceinline__ float fexp(float x) {
    float y = fmaxf(x * 1.44269504088896f, -126.0f);
    float k = rintf(y);
    float f = y - k;
    float p = 1.3333558146e-3f;
    p = fmaf(p, f, 9.6181291076e-3f);
    p = fmaf(p, f, 5.5504108664e-2f);
    p = fmaf(p, f, 2.4022650696e-1f);
    p = fmaf(p, f, 6.9314718056e-1f);
    p = fmaf(p, f, 1.0f);
    return p * __int_as_float(((int)k + 127) << 23);
}
__device__ __forceinline__ uint32_t pk2h(float lo, float hi) {
    uint32_t d; asm("cvt.rn.f16x2.f32 %0, %1, %2;" : "=r"(d) : "f"(hi), "f"(lo)); return d;
}
__device__ __forceinline__ uint32_t smem_u32(const void* p) {
    uint32_t a;
    asm("{ .reg .u64 t; cvta.to.shared.u64 t, %1; cvt.u32.u64 %0, t; }" : "=r"(a) : "l"(p));
    return a;
}
#define CP16(dst, src) \
    asm volatile("cp.async.cg.shared.global [%0], [%1], 16;" :: "r"(dst), "l"(src))
#define CP_COMMIT() asm volatile("cp.async.commit_group;" ::: "memory")
#define CP_WAIT0()  asm volatile("cp.async.wait_group 0;" ::: "memory")

// -------------------- prep ----------------------------------------------------
__global__ void init_kernel(int Nn) {
    int i = blockIdx.x * blockDim.x + threadIdx.x;
    if (i < Nn) g_cmax[i] = 0u;
    if (i == 0) g_logdmax = 0;
}

__global__ void proj_kernel(const float* __restrict__ state, const float* __restrict__ W) {
    __shared__ float s[D_DIM];
    int b = blockIdx.x, j = threadIdx.x;
    s[j] = state[b * D_DIM + j];
    __syncthreads();
    const float* wr = W + j * D_DIM;
    float acc = 0.f;
#pragma unroll 16
    for (int d = 0; d < D_DIM; ++d) acc = fmaf(s[d], wr[d], acc);
    g_projh[b * D_DIM + j] = __float2half_rn(acc);
}

__global__ void bias_kernel(const float* __restrict__ depths,
                            const float* __restrict__ gate, int Nn) {
    int i = blockIdx.x * 256 + threadIdx.x;
    float lv = 0.f;
    if (i < Nn) {
        float d = depths[i], g = gate[i];
        g_bias[i] = logf(fmaxf(d, 1e-8f)) + logf(fmaxf(g, 1e-8f));
        lv = log1pf(d);
    }
    __shared__ float red[256];
    red[threadIdx.x] = lv;
    __syncthreads();
#pragma unroll
    for (int o = 128; o > 0; o >>= 1) {
        if (threadIdx.x < o) red[threadIdx.x] = fmaxf(red[threadIdx.x], red[threadIdx.x + o]);
        __syncthreads();
    }
    if (threadIdx.x == 0) atomicMax(&g_logdmax, __float_as_int(red[0]));
}

__global__ void patprep_kernel(const float* __restrict__ pat, int Nn) {
    long i = (long)blockIdx.x * 256 + threadIdx.x;
    long e0 = i * 4;
    long n = e0 >> 8;
    float4 v = (n < Nn) ? *(const float4*)&pat[e0] : make_float4(0.f, 0.f, 0.f, 0.f);
    *(uint2*)&g_patf[e0] = make_uint2(pk2h(v.x, v.y), pk2h(v.z, v.w));
}

// -------------------- gemm1: e16 = exp(z - pm_tile), z = proj@pat^T + bias ----
// CTA tile 128(M) x 256(N), 16 warps (4x4 of 32x64), k-chunks 64, double buffer.
// smem/stage: A[128][72]h 18432 + B[256][72]h 36864 = 55296; x2 = 110592
// epilogue overlay: float Cs[128][264] = 135168
#define SM1_BYTES 135168
#define G1_STAGE 55296
__global__ __launch_bounds__(512) void gemm1_kernel(int Nn) {
    extern __shared__ char sm[];
    const uint32_t sb = smem_u32(sm);
    float* Cs = (float*)sm;
    const int tid = threadIdx.x, wid = tid >> 5;
    const int wm = wid >> 2, wn = wid & 3;              // 4 x 4 warps, tile 32 x 64
    const int m0 = blockIdx.x * 128;
    const long n0 = (long)blockIdx.y * 256;

    wmma::fragment<wmma::accumulator, 16, 16, 16, float> acc[2][4];
#pragma unroll
    for (int mi = 0; mi < 2; ++mi)
#pragma unroll
        for (int ni = 0; ni < 4; ++ni) wmma::fill_fragment(acc[mi][ni], 0.0f);

    const int ar = tid >> 2, ac = (tid & 3) * 16;       // A: 32B per thread
    const int br = tid >> 1, bc = (tid & 1) * 32;       // B: 64B per thread
    const char* sA = (const char*)(g_projh + (size_t)(m0 + ar) * D_DIM + ac);
    const char* sB = (const char*)(g_patf + (n0 + br) * D_DIM + bc);
    const uint32_t dA = sb + ar * 144 + ac * 2;
    const uint32_t dB = sb + 18432 + br * 144 + bc * 2;

#define G1_ISSUE(c, buf) do { \
        long ob = (long)(c) * 128; \
        uint32_t da = dA + (buf) * G1_STAGE, db = dB + (buf) * G1_STAGE; \
        CP16(da, sA + ob); CP16(da + 16, sA + ob + 16); \
        CP16(db, sB + ob); CP16(db + 16, sB + ob + 16); \
        CP16(db + 32, sB + ob + 32); CP16(db + 48, sB + ob + 48); \
        CP_COMMIT(); } while (0)

    G1_ISSUE(0, 0);
    CP_WAIT0();
    __syncthreads();

    for (int c = 0; c < 4; ++c) {
        const int cur = c & 1;
        if (c < 3) G1_ISSUE(c + 1, cur ^ 1);
        const __half* Ah = (const __half*)(sm + cur * G1_STAGE);
        const __half* Bs = (const __half*)(sm + cur * G1_STAGE + 18432);
#pragma unroll
        for (int kk = 0; kk < 64; kk += 16) {
            wmma::fragment<wmma::matrix_a, 16, 16, 16, __half, wmma::row_major> ah[2];
            wmma::fragment<wmma::matrix_b, 16, 16, 16, __half, wmma::col_major> bh[4];
#pragma unroll
            for (int mi = 0; mi < 2; ++mi)
                wmma::load_matrix_sync(ah[mi], &Ah[(wm * 32 + mi * 16) * 72 + kk], 72);
#pragma unroll
            for (int ni = 0; ni < 4; ++ni)
                wmma::load_matrix_sync(bh[ni], &Bs[(wn * 64 + ni * 16) * 72 + kk], 72);
#pragma unroll
            for (int mi = 0; mi < 2; ++mi)
#pragma unroll
                for (int ni = 0; ni < 4; ++ni)
                    wmma::mma_sync(acc[mi][ni], ah[mi], bh[ni], acc[mi][ni]);
        }
        if (c < 3) CP_WAIT0();
        __syncthreads();
    }

#pragma unroll
    for (int mi = 0; mi < 2; ++mi)
#pragma unroll
        for (int ni = 0; ni < 4; ++ni)
            wmma::store_matrix_sync(&Cs[(wm * 32 + mi * 16) * 264 + wn * 64 + ni * 16],
                                    acc[mi][ni], 264, wmma::mem_row_major);
    __syncthreads();

    // epilogue: pm = row-tile max of (c + bias); e16 = exp(z - pm); sum; store fp16
    const int r2 = tid >> 2, hc = (tid & 3) * 64;
    const int m = m0 + r2;
    const float* crow = Cs + r2 * 264 + hc;
    float vmax = -3.0e38f;
#pragma unroll
    for (int j = 0; j < 64; j += 4) {
        long n = n0 + hc + j;
        if (n + 4 <= Nn) {
            float4 b4 = *(const float4*)&g_bias[n];
            float4 c4 = *(const float4*)&crow[j];
            vmax = fmaxf(vmax, fmaxf(fmaxf(c4.x + b4.x, c4.y + b4.y),
                                     fmaxf(c4.z + b4.z, c4.w + b4.w)));
        } else {
            for (int q = 0; q < 4; ++q)
                if (n + q < Nn) vmax = fmaxf(vmax, crow[j + q] + g_bias[n + q]);
        }
    }
    float pmv = fmaxf(vmax, __shfl_xor_sync(0xffffffffu, vmax, 1));
    pmv = fmaxf(pmv, __shfl_xor_sync(0xffffffffu, pmv, 2));

    float s = 0.f;
    __half* erow = g_e16 + (size_t)m * NPAD + n0 + hc;
#pragma unroll
    for (int j = 0; j < 64; j += 8) {
        long n = n0 + hc + j;
        uint32_t hh[4];
        if (n + 8 <= Nn) {
            float4 ba = *(const float4*)&g_bias[n];
            float4 ca = *(const float4*)&crow[j];
            float4 bb = *(const float4*)&g_bias[n + 4];
            float4 cb = *(const float4*)&crow[j + 4];
            float e0 = fexp(ca.x + ba.x - pmv), e1 = fexp(ca.y + ba.y - pmv);
            float e2 = fexp(ca.z + ba.z - pmv), e3 = fexp(ca.w + ba.w - pmv);
            float e4 = fexp(cb.x + bb.x - pmv), e5 = fexp(cb.y + bb.y - pmv);
            float e6 = fexp(cb.z + bb.z - pmv), e7 = fexp(cb.w + bb.w - pmv);
            s += (e0 + e1) + (e2 + e3) + (e4 + e5) + (e6 + e7);
            hh[0] = pk2h(e0, e1); hh[1] = pk2h(e2, e3);
            hh[2] = pk2h(e4, e5); hh[3] = pk2h(e6, e7);
        } else {
            float e[8];
            for (int q = 0; q < 8; ++q) {
                long nn = n + q;
                e[q] = (nn < Nn) ? fexp(crow[j + q] + g_bias[nn] - pmv) : 0.f;
                s += e[q];
            }
            hh[0] = pk2h(e[0], e[1]); hh[1] = pk2h(e[2], e[3]);
            hh[2] = pk2h(e[4], e[5]); hh[3] = pk2h(e[6], e[7]);
        }
        *(uint4*)&erow[j] = make_uint4(hh[0], hh[1], hh[2], hh[3]);
    }
    s += __shfl_xor_sync(0xffffffffu, s, 1);
    s += __shfl_xor_sync(0xffffffffu, s, 2);
    if ((tid & 3) == 0) {
        g_pm[(size_t)blockIdx.y * B_DIM + m] = pmv;
        g_ps[(size_t)blockIdx.y * B_DIM + m] = s;
    }
}

// -------------------- lse merge -------------------------------------------------
__global__ void lse_merge_kernel(int ntiles) {
    int m = blockIdx.x * 256 + threadIdx.x;
    if (m >= B_DIM) return;
    float M = -3.0e38f;
    for (int t = 0; t < ntiles; ++t) M = fmaxf(M, g_pm[(size_t)t * B_DIM + m]);
    float S = 0.f;
    for (int t = 0; t < ntiles; ++t) {
        float pm = g_pm[(size_t)t * B_DIM + m];
        if (pm > -1.0e38f) S += g_ps[(size_t)t * B_DIM + m] * fexp(pm - M);
    }
    g_L[m] = M + logf(S);
}

// -------------------- gemm2: part = (e16 * s_tile) @ pat + colmax ---------------
// smem/stage: A[128][72]h 18432 + B[64][264]h 33792 = 52224; x2 = 104448
// epilogue overlay: float Cs[128][264] = 135168
#define SM2_BYTES 135168
#define G2_STAGE 52224
__global__ __launch_bounds__(512) void gemm2_kernel(int Nn, int CHv) {
    extern __shared__ char sm[];
    const uint32_t sb = smem_u32(sm);
    float* Cs = (float*)sm;
    __shared__ unsigned scm[2][64];
    const int tid = threadIdx.x, wid = tid >> 5, lane = tid & 31;
    const int wm = wid >> 2, wd = wid & 3;              // 4 x 4 warps, tile 32 x 64
    const int m0 = blockIdx.x * 128;
    const int sp = blockIdx.y;
    const int ns = sp * CHv, ne = min(ns + CHv, Nn);
    if (ns >= ne) {
        const size_t pb = ((size_t)sp * B_DIM + m0) * D_DIM;
        for (int i = tid; i < 128 * D_DIM / 4; i += 512)
            *(float4*)&g_part[pb + (size_t)i * 4] = make_float4(0.f, 0.f, 0.f, 0.f);
        return;
    }
    const int nch = (ne - ns + 63) / 64;

    wmma::fragment<wmma::accumulator, 16, 16, 16, float> acc[2][4];
#pragma unroll
    for (int mi = 0; mi < 2; ++mi)
#pragma unroll
        for (int ni = 0; ni < 4; ++ni) wmma::fill_fragment(acc[mi][ni], 0.0f);

    const int r = tid >> 2, ng = (tid & 3) * 16;
    const float Lm = g_L[m0 + r];
    const __half* erow = g_e16 + (size_t)(m0 + r) * NPAD;
    const uint32_t dA = sb + r * 144 + ng * 2;
    if (tid < 64) { scm[0][tid] = 0u; scm[1][tid] = 0u; }
    __syncthreads();

    uint32_t ev[8];   // 16 fp16 e-values

    // prefetch e16 for a chunk into registers (pad region is zero-filled)
#define G2_ZLOAD(k0v) do { \
        long nbase = (long)(k0v) + ng; \
        *(uint4*)&ev[0] = *(const uint4*)&erow[nbase]; \
        *(uint4*)&ev[4] = *(const uint4*)&erow[nbase + 8]; \
    } while (0)

    // scale by s = exp(pm_tile - L), store fp16 weights to A smem, colmax into scm
#define G2_WSTORE(k0v, buf, chpar) do { \
        int t = (int)((k0v) >> 8); \
        float sfac = fexp(g_pm[(size_t)t * B_DIM + m0 + r] - Lm); \
        __half2 sh2 = __float2half2_rn(sfac); \
        uint32_t h2v[8]; \
        float w[16]; \
        for (int j = 0; j < 8; ++j) { \
            __half2 a = *reinterpret_cast<__half2*>(&ev[j]); \
            __half2 pr = __hmul2(a, sh2); \
            h2v[j] = *reinterpret_cast<uint32_t*>(&pr); \
            float2 f = __half22float2(pr); \
            w[2 * j] = f.x; w[2 * j + 1] = f.y; \
        } \
        uint32_t doff = dA + (buf) * G2_STAGE - sb; \
        *(uint4*)(sm + doff) = make_uint4(h2v[0], h2v[1], h2v[2], h2v[3]); \
        *(uint4*)(sm + doff + 16) = make_uint4(h2v[4], h2v[5], h2v[6], h2v[7]); \
        uint32_t cm[16]; \
        for (int j = 0; j < 16; ++j) cm[j] = __float_as_uint(w[j]); \
        for (int off = 4; off <= 16; off <<= 1) \
            for (int j = 0; j < 16; ++j) { \
                uint32_t o = __shfl_xor_sync(0xffffffffu, cm[j], off); \
                cm[j] = (o > cm[j]) ? o : cm[j]; \
            } \
        if (lane < 4) \
            for (int j = 0; j < 16; ++j) atomicMax(&scm[chpar][lane * 16 + j], cm[j]); \
    } while (0)

#define G2_BISSUE(k0v, buf) do { \
        uint32_t base = sb + (buf) * G2_STAGE + 18432; \
        const char* psrc = (const char*)(g_patf + (size_t)(k0v) * D_DIM); \
        for (int k = 0; k < 4; ++k) { \
            int s0 = tid + k * 512; \
            CP16(base + (s0 >> 5) * 528 + (s0 & 31) * 16, psrc + (s0 >> 5) * 512 + (s0 & 31) * 16); \
        } \
        CP_COMMIT(); } while (0)

    G2_BISSUE(ns, 0);
    G2_ZLOAD(ns);
    G2_WSTORE(ns, 0, 0);
    CP_WAIT0();
    __syncthreads();

    for (int ci = 0; ci < nch; ++ci) {
        const int cur = ci & 1;
        if (ci > 0 && tid < 64) {
            int n = ns + (ci - 1) * 64 + tid;
            unsigned v = scm[cur ^ 1][tid];
            if (n < Nn && v) atomicMax(&g_cmax[n], v);
            scm[cur ^ 1][tid] = 0u;
        }
        const bool pre = (ci + 1 < nch);
        if (pre) {
            G2_BISSUE(ns + (ci + 1) * 64, cur ^ 1);
            G2_ZLOAD(ns + (ci + 1) * 64);       // prefetch e16 under MMA
        }

        const __half* Ah = (const __half*)(sm + cur * G2_STAGE);
        const __half* Bs = (const __half*)(sm + cur * G2_STAGE + 18432);
#pragma unroll
        for (int kk = 0; kk < 64; kk += 16) {
            wmma::fragment<wmma::matrix_a, 16, 16, 16, __half, wmma::row_major> ah[2];
            wmma::fragment<wmma::matrix_b, 16, 16, 16, __half, wmma::row_major> bh[4];
#pragma unroll
            for (int mi = 0; mi < 2; ++mi)
                wmma::load_matrix_sync(ah[mi], &Ah[(wm * 32 + mi * 16) * 72 + kk], 72);
#pragma unroll
            for (int ni = 0; ni < 4; ++ni)
                wmma::load_matrix_sync(bh[ni], &Bs[kk * 264 + wd * 64 + ni * 16], 264);
#pragma unroll
            for (int mi = 0; mi < 2; ++mi)
#pragma unroll
                for (int ni = 0; ni < 4; ++ni)
                    wmma::mma_sync(acc[mi][ni], ah[mi], bh[ni], acc[mi][ni]);
        }
        if (pre) {
            G2_WSTORE(ns + (ci + 1) * 64, cur ^ 1, cur ^ 1);
            CP_WAIT0();
        }
        __syncthreads();
    }
    if (tid < 64) {
        int n = ns + (nch - 1) * 64 + tid;
        unsigned v = scm[(nch - 1) & 1][tid];
        if (n < Nn && v) atomicMax(&g_cmax[n], v);
    }

#pragma unroll
    for (int mi = 0; mi < 2; ++mi)
#pragma unroll
        for (int ni = 0; ni < 4; ++ni)
            wmma::store_matrix_sync(&Cs[(wm * 32 + mi * 16) * 264 + wd * 64 + ni * 16],
                                    acc[mi][ni], 264, wmma::mem_row_major);
    __syncthreads();
    const int rr = tid >> 2, cgr = (tid & 3) * 64;
    const size_t ob = ((size_t)sp * B_DIM + m0 + rr) * D_DIM + cgr;
#pragma unroll
    for (int j = 0; j < 64; j += 4)
        *(float4*)&g_part[ob + j] = *(const float4*)&Cs[rr * 264 + cgr + j];
}

// -------------------- reductions / output --------------------------------------
__global__ void reduce_ret_kernel(float* __restrict__ out) {
    size_t i = (size_t)blockIdx.x * 256 + threadIdx.x;
    float4 s = make_float4(0.f, 0.f, 0.f, 0.f);
    for (int sp = 0; sp < NSPLIT; ++sp) {
        float4 v = *(const float4*)&g_part[(size_t)sp * (B_DIM * D_DIM) + i * 4];
        s.x += v.x; s.y += v.y; s.z += v.z; s.w += v.w;
    }
    *(float4*)&out[i * 4] = s;
}

__global__ void depths_kernel(const float* __restrict__ depths,
                              float* __restrict__ out, int Nn) {
    int i = blockIdx.x * 256 + threadIdx.x;
    if (i >= Nn) return;
    float d = depths[i];
    float maxw = __uint_as_float(g_cmax[i]);
    float dom = log1pf(d) / fmaxf(__int_as_float(g_logdmax), 1e-8f);
    float rate = 0.01f * (1.0f - 0.7f * dom);
    out[B_DIM * D_DIM + i] = d + ((maxw > 0.1f) ? rate * maxw : 0.0f);
}

extern "C" void kernel_launch(void* const* d_in, const int* in_sizes, int n_in,
                              void* d_out, int out_size) {
    const float* state  = (const float*)d_in[0];
    const float* W      = (const float*)d_in[1];
    const float* pat    = (const float*)d_in[2];
    const float* depths = (const float*)d_in[3];
    const float* gate   = (const float*)d_in[4];
    float* out = (float*)d_out;
    const int Nn = in_sizes[3];

    cudaFuncSetAttribute(gemm1_kernel, cudaFuncAttributeMaxDynamicSharedMemorySize, SM1_BYTES);
    cudaFuncSetAttribute(gemm2_kernel, cudaFuncAttributeMaxDynamicSharedMemorySize, SM2_BYTES);

    const int nbN = (Nn + 255) / 256;
    init_kernel<<<nbN, 256>>>(Nn);
    proj_kernel<<<B_DIM, 256>>>(state, W);
    bias_kernel<<<nbN, 256>>>(depths, gate, Nn);
    patprep_kernel<<<(NPAD * D_DIM / 4) / 256, 256>>>(pat, Nn);

    gemm1_kernel<<<dim3(B_DIM / 128, NT1), 512, SM1_BYTES>>>(Nn);
    lse_merge_kernel<<<B_DIM / 256, 256>>>(NT1);

    const int CHv = ((Nn + NSPLIT * 64 - 1) / (NSPLIT * 64)) * 64;
    gemm2_kernel<<<dim3(B_DIM / 128, NSPLIT), 512, SM2_BYTES>>>(Nn, CHv);

    reduce_ret_kernel<<<(B_DIM * D_DIM / 4) / 256, 256>>>(out);
    depths_kernel<<<nbN, 256>>>(depths, out, Nn);
}

// round 12
// speedup vs baseline: 1.2096x; 1.0013x over previous
#include <cuda_runtime.h>
#include <cuda_fp16.h>
#include <mma.h>
#include <math.h>
#include <stdint.h>

using namespace nvcuda;

#define B_DIM 1024
#define D_DIM 256
#define NPAD  100352
#define NSPLIT 37
#define NT1 784            // NPAD / 128

__device__ __half g_projh[B_DIM * D_DIM];
__device__ float g_bias[NPAD];
__device__ __half g_e16[(size_t)B_DIM * NPAD];   // exp(z - pm_tile), fp16
__device__ float g_L[B_DIM];
__device__ float g_pm[(size_t)NT1 * B_DIM];
__device__ float g_ps[(size_t)NT1 * B_DIM];
__device__ __half g_patf[(size_t)NPAD * D_DIM];
__device__ float g_part[(size_t)NSPLIT * B_DIM * D_DIM];
__device__ unsigned g_cmax[NPAD];
__device__ int g_logdmax;

// fast exp on FMA pipe (rel err ~3e-6)
__device__ __forceinline__ float fexp(float x) {
    float y = fmaxf(x * 1.44269504088896f, -126.0f);
    float k = rintf(y);
    float f = y - k;
    float p = 1.3333558146e-3f;
    p = fmaf(p, f, 9.6181291076e-3f);
    p = fmaf(p, f, 5.5504108664e-2f);
    p = fmaf(p, f, 2.4022650696e-1f);
    p = fmaf(p, f, 6.9314718056e-1f);
    p = fmaf(p, f, 1.0f);
    return p * __int_as_float(((int)k + 127) << 23);
}
__device__ __forceinline__ uint32_t pk2h(float lo, float hi) {
    uint32_t d; asm("cvt.rn.f16x2.f32 %0, %1, %2;" : "=r"(d) : "f"(hi), "f"(lo)); return d;
}
__device__ __forceinline__ uint32_t smem_u32(const void* p) {
    uint32_t a;
    asm("{ .reg .u64 t; cvta.to.shared.u64 t, %1; cvt.u32.u64 %0, t; }" : "=r"(a) : "l"(p));
    return a;
}
#define CP16(dst, src) \
    asm volatile("cp.async.cg.shared.global [%0], [%1], 16;" :: "r"(dst), "l"(src))
#define CP_COMMIT() asm volatile("cp.async.commit_group;" ::: "memory")
#define CP_WAIT0()  asm volatile("cp.async.wait_group 0;" ::: "memory")

// -------------------- prep ----------------------------------------------------
__global__ void init_kernel(int Nn) {
    int i = blockIdx.x * blockDim.x + threadIdx.x;
    if (i < Nn) g_cmax[i] = 0u;
    if (i == 0) g_logdmax = 0;
}

__global__ void proj_kernel(const float* __restrict__ state, const float* __restrict__ W) {
    __shared__ float s[D_DIM];
    int b = blockIdx.x, j = threadIdx.x;
    s[j] = state[b * D_DIM + j];
    __syncthreads();
    const float* wr = W + j * D_DIM;
    float acc = 0.f;
#pragma unroll 16
    for (int d = 0; d < D_DIM; ++d) acc = fmaf(s[d], wr[d], acc);
    g_projh[b * D_DIM + j] = __float2half_rn(acc);
}

__global__ void bias_kernel(const float* __restrict__ depths,
                            const float* __restrict__ gate, int Nn) {
    int i = blockIdx.x * 256 + threadIdx.x;
    float lv = 0.f;
    if (i < Nn) {
        float d = depths[i], g = gate[i];
        g_bias[i] = logf(fmaxf(d, 1e-8f)) + logf(fmaxf(g, 1e-8f));
        lv = log1pf(d);
    }
    __shared__ float red[256];
    red[threadIdx.x] = lv;
    __syncthreads();
#pragma unroll
    for (int o = 128; o > 0; o >>= 1) {
        if (threadIdx.x < o) red[threadIdx.x] = fmaxf(red[threadIdx.x], red[threadIdx.x + o]);
        __syncthreads();
    }
    if (threadIdx.x == 0) atomicMax(&g_logdmax, __float_as_int(red[0]));
}

__global__ void patprep_kernel(const float* __restrict__ pat, int Nn) {
    long i = (long)blockIdx.x * 256 + threadIdx.x;
    long e0 = i * 4;
    long n = e0 >> 8;
    float4 v = (n < Nn) ? *(const float4*)&pat[e0] : make_float4(0.f, 0.f, 0.f, 0.f);
    *(uint2*)&g_patf[e0] = make_uint2(pk2h(v.x, v.y), pk2h(v.z, v.w));
}

// -------------------- gemm1: e16 = exp(z - pm_tile), z = proj@pat^T + bias ----
// CTA tile 128(M) x 128(N), 8 warps (4x2 of 32x64), k-chunks 64, double buffer.
// smem/stage: A[128][72]h 18432 + B[128][72]h 18432 = 36864; x2 = 73728
// epilogue overlay: float Cs[128][136] = 69632  -> 2 CTAs/SM
#define SM1_BYTES 73728
#define G1_STAGE 36864
__global__ __launch_bounds__(256, 2) void gemm1_kernel(int Nn) {
    extern __shared__ char sm[];
    const uint32_t sb = smem_u32(sm);
    float* Cs = (float*)sm;
    const int tid = threadIdx.x, wid = tid >> 5;
    const int wm = wid >> 1, wn = wid & 1;              // 4 x 2 warps, tile 32 x 64
    const int m0 = blockIdx.x * 128;
    const long n0 = (long)blockIdx.y * 128;

    wmma::fragment<wmma::accumulator, 16, 16, 16, float> acc[2][4];
#pragma unroll
    for (int mi = 0; mi < 2; ++mi)
#pragma unroll
        for (int ni = 0; ni < 4; ++ni) wmma::fill_fragment(acc[mi][ni], 0.0f);

    const int ar = tid >> 1, ac = (tid & 1) * 32;       // 64B per thread per operand
    const char* sA = (const char*)(g_projh + (size_t)(m0 + ar) * D_DIM + ac);
    const char* sB = (const char*)(g_patf + (n0 + ar) * D_DIM + ac);
    const uint32_t dA = sb + ar * 144 + ac * 2;
    const uint32_t dB = sb + 18432 + ar * 144 + ac * 2;

#define G1_ISSUE(c, buf) do { \
        long ob = (long)(c) * 128; \
        uint32_t da = dA + (buf) * G1_STAGE, db = dB + (buf) * G1_STAGE; \
        CP16(da, sA + ob); CP16(da + 16, sA + ob + 16); \
        CP16(da + 32, sA + ob + 32); CP16(da + 48, sA + ob + 48); \
        CP16(db, sB + ob); CP16(db + 16, sB + ob + 16); \
        CP16(db + 32, sB + ob + 32); CP16(db + 48, sB + ob + 48); \
        CP_COMMIT(); } while (0)

    G1_ISSUE(0, 0);
    CP_WAIT0();
    __syncthreads();

    for (int c = 0; c < 4; ++c) {
        const int cur = c & 1;
        if (c < 3) G1_ISSUE(c + 1, cur ^ 1);
        const __half* Ah = (const __half*)(sm + cur * G1_STAGE);
        const __half* Bs = (const __half*)(sm + cur * G1_STAGE + 18432);
#pragma unroll
        for (int kk = 0; kk < 64; kk += 16) {
            wmma::fragment<wmma::matrix_a, 16, 16, 16, __half, wmma::row_major> ah[2];
            wmma::fragment<wmma::matrix_b, 16, 16, 16, __half, wmma::col_major> bh[4];
#pragma unroll
            for (int mi = 0; mi < 2; ++mi)
                wmma::load_matrix_sync(ah[mi], &Ah[(wm * 32 + mi * 16) * 72 + kk], 72);
#pragma unroll
            for (int ni = 0; ni < 4; ++ni)
                wmma::load_matrix_sync(bh[ni], &Bs[(wn * 64 + ni * 16) * 72 + kk], 72);
#pragma unroll
            for (int mi = 0; mi < 2; ++mi)
#pragma unroll
                for (int ni = 0; ni < 4; ++ni)
                    wmma::mma_sync(acc[mi][ni], ah[mi], bh[ni], acc[mi][ni]);
        }
        if (c < 3) CP_WAIT0();
        __syncthreads();
    }

#pragma unroll
    for (int mi = 0; mi < 2; ++mi)
#pragma unroll
        for (int ni = 0; ni < 4; ++ni)
            wmma::store_matrix_sync(&Cs[(wm * 32 + mi * 16) * 136 + wn * 64 + ni * 16],
                                    acc[mi][ni], 136, wmma::mem_row_major);
    __syncthreads();

    // epilogue: pm = row-tile max of (c + bias); e16 = exp(z - pm); sum; store fp16
    const int r2 = tid >> 1, hc = (tid & 1) * 64;
    const int m = m0 + r2;
    const float* crow = Cs + r2 * 136 + hc;
    float vmax = -3.0e38f;
#pragma unroll
    for (int j = 0; j < 64; j += 4) {
        long n = n0 + hc + j;
        if (n + 4 <= Nn) {
            float4 b4 = *(const float4*)&g_bias[n];
            float4 c4 = *(const float4*)&crow[j];
            vmax = fmaxf(vmax, fmaxf(fmaxf(c4.x + b4.x, c4.y + b4.y),
                                     fmaxf(c4.z + b4.z, c4.w + b4.w)));
        } else {
            for (int q = 0; q < 4; ++q)
                if (n + q < Nn) vmax = fmaxf(vmax, crow[j + q] + g_bias[n + q]);
        }
    }
    float pmv = fmaxf(vmax, __shfl_xor_sync(0xffffffffu, vmax, 1));

    float s = 0.f;
    __half* erow = g_e16 + (size_t)m * NPAD + n0 + hc;
#pragma unroll
    for (int j = 0; j < 64; j += 8) {
        long n = n0 + hc + j;
        uint32_t hh[4];
        if (n + 8 <= Nn) {
            float4 ba = *(const float4*)&g_bias[n];
            float4 ca = *(const float4*)&crow[j];
            float4 bb = *(const float4*)&g_bias[n + 4];
            float4 cb = *(const float4*)&crow[j + 4];
            float e0 = fexp(ca.x + ba.x - pmv), e1 = fexp(ca.y + ba.y - pmv);
            float e2 = fexp(ca.z + ba.z - pmv), e3 = fexp(ca.w + ba.w - pmv);
            float e4 = fexp(cb.x + bb.x - pmv), e5 = fexp(cb.y + bb.y - pmv);
            float e6 = fexp(cb.z + bb.z - pmv), e7 = fexp(cb.w + bb.w - pmv);
            s += (e0 + e1) + (e2 + e3) + (e4 + e5) + (e6 + e7);
            hh[0] = pk2h(e0, e1); hh[1] = pk2h(e2, e3);
            hh[2] = pk2h(e4, e5); hh[3] = pk2h(e6, e7);
        } else {
            float e[8];
            for (int q = 0; q < 8; ++q) {
                long nn = n + q;
                e[q] = (nn < Nn) ? fexp(crow[j + q] + g_bias[nn] - pmv) : 0.f;
                s += e[q];
            }
            hh[0] = pk2h(e[0], e[1]); hh[1] = pk2h(e[2], e[3]);
            hh[2] = pk2h(e[4], e[5]); hh[3] = pk2h(e[6], e[7]);
        }
        *(uint4*)&erow[j] = make_uint4(hh[0], hh[1], hh[2], hh[3]);
    }
    s += __shfl_xor_sync(0xffffffffu, s, 1);
    if ((tid & 1) == 0) {
        g_pm[(size_t)blockIdx.y * B_DIM + m] = pmv;
        g_ps[(size_t)blockIdx.y * B_DIM + m] = s;
    }
}

// -------------------- lse merge -------------------------------------------------
__global__ void lse_merge_kernel(int ntiles) {
    int m = blockIdx.x * 256 + threadIdx.x;
    if (m >= B_DIM) return;
    float M = -3.0e38f;
    for (int t = 0; t < ntiles; ++t) M = fmaxf(M, g_pm[(size_t)t * B_DIM + m]);
    float S = 0.f;
    for (int t = 0; t < ntiles; ++t) {
        float pm = g_pm[(size_t)t * B_DIM + m];
        if (pm > -1.0e38f) S += g_ps[(size_t)t * B_DIM + m] * fexp(pm - M);
    }
    g_L[m] = M + logf(S);
}

// -------------------- gemm2: part = (e16 * s_tile) @ pat + colmax ---------------
// CTA tile 64(M) x 256(D), 8 warps (2x4 of 32x64), k-chunk 64, double buffer.
// smem/stage: A[64][72]h 9216 + B[64][264]h 33792 = 43008; x2 = 86016 -> 2 CTAs/SM
// epilogue overlay: float Cs[64][264] = 67584
#define SM2_BYTES 86016
#define G2_STAGE 43008
__global__ __launch_bounds__(256, 2) void gemm2_kernel(int Nn, int CHv) {
    extern __shared__ char sm[];
    const uint32_t sb = smem_u32(sm);
    float* Cs = (float*)sm;
    __shared__ unsigned scm[2][64];
    const int tid = threadIdx.x, wid = tid >> 5, lane = tid & 31;
    const int wm = wid >> 2, wd = wid & 3;              // 2 x 4 warps, tile 32 x 64
    const int m0 = blockIdx.x * 64;
    const int sp = blockIdx.y;
    const int ns = sp * CHv, ne = min(ns + CHv, Nn);
    if (ns >= ne) {
        const size_t pb = ((size_t)sp * B_DIM + m0) * D_DIM;
        for (int i = tid; i < 64 * D_DIM / 4; i += 256)
            *(float4*)&g_part[pb + (size_t)i * 4] = make_float4(0.f, 0.f, 0.f, 0.f);
        return;
    }
    const int nch = (ne - ns + 63) / 64;

    wmma::fragment<wmma::accumulator, 16, 16, 16, float> acc[2][4];
#pragma unroll
    for (int mi = 0; mi < 2; ++mi)
#pragma unroll
        for (int ni = 0; ni < 4; ++ni) wmma::fill_fragment(acc[mi][ni], 0.0f);

    const int r = tid >> 2, ng = (tid & 3) * 16;
    const float Lm = g_L[m0 + r];
    const __half* erow = g_e16 + (size_t)(m0 + r) * NPAD;
    const uint32_t dA = sb + r * 144 + ng * 2;
    if (tid < 64) { scm[0][tid] = 0u; scm[1][tid] = 0u; }
    __syncthreads();

    uint32_t ev[8];   // 16 fp16 e-values

#define G2_ZLOAD(k0v) do { \
        long nbase = (long)(k0v) + ng; \
        *(uint4*)&ev[0] = *(const uint4*)&erow[nbase]; \
        *(uint4*)&ev[4] = *(const uint4*)&erow[nbase + 8]; \
    } while (0)

#define G2_WSTORE(k0v, buf, chpar) do { \
        int t = (int)((k0v) >> 7); \
        float sfac = fexp(g_pm[(size_t)t * B_DIM + m0 + r] - Lm); \
        __half2 sh2 = __float2half2_rn(sfac); \
        uint32_t h2v[8]; \
        float w[16]; \
        for (int j = 0; j < 8; ++j) { \
            __half2 a = *reinterpret_cast<__half2*>(&ev[j]); \
            __half2 pr = __hmul2(a, sh2); \
            h2v[j] = *reinterpret_cast<uint32_t*>(&pr); \
            float2 f = __half22float2(pr); \
            w[2 * j] = f.x; w[2 * j + 1] = f.y; \
        } \
        uint32_t doff = dA + (buf) * G2_STAGE - sb; \
        *(uint4*)(sm + doff) = make_uint4(h2v[0], h2v[1], h2v[2], h2v[3]); \
        *(uint4*)(sm + doff + 16) = make_uint4(h2v[4], h2v[5], h2v[6], h2v[7]); \
        uint32_t cm[16]; \
        for (int j = 0; j < 16; ++j) cm[j] = __float_as_uint(w[j]); \
        for (int off = 4; off <= 16; off <<= 1) \
            for (int j = 0; j < 16; ++j) { \
                uint32_t o = __shfl_xor_sync(0xffffffffu, cm[j], off); \
                cm[j] = (o > cm[j]) ? o : cm[j]; \
            } \
        if (lane < 4) \
            for (int j = 0; j < 16; ++j) atomicMax(&scm[chpar][lane * 16 + j], cm[j]); \
    } while (0)

#define G2_BISSUE(k0v, buf) do { \
        uint32_t base = sb + (buf) * G2_STAGE + 9216; \
        const char* psrc = (const char*)(g_patf + (size_t)(k0v) * D_DIM); \
        for (int k = 0; k < 8; ++k) { \
            int s0 = tid + k * 256; \
            CP16(base + (s0 >> 5) * 528 + (s0 & 31) * 16, psrc + (s0 >> 5) * 512 + (s0 & 31) * 16); \
        } \
        CP_COMMIT(); } while (0)

    G2_BISSUE(ns, 0);
    G2_ZLOAD(ns);
    G2_WSTORE(ns, 0, 0);
    CP_WAIT0();
    __syncthreads();

    for (int ci = 0; ci < nch; ++ci) {
        const int cur = ci & 1;
        if (ci > 0 && tid < 64) {
            int n = ns + (ci - 1) * 64 + tid;
            unsigned v = scm[cur ^ 1][tid];
            if (n < Nn && v) atomicMax(&g_cmax[n], v);
            scm[cur ^ 1][tid] = 0u;
        }
        const bool pre = (ci + 1 < nch);
        if (pre) {
            G2_BISSUE(ns + (ci + 1) * 64, cur ^ 1);
            G2_ZLOAD(ns + (ci + 1) * 64);       // prefetch e16 under MMA
        }

        const __half* Ah = (const __half*)(sm + cur * G2_STAGE);
        const __half* Bs = (const __half*)(sm + cur * G2_STAGE + 9216);
#pragma unroll
        for (int kk = 0; kk < 64; kk += 16) {
            wmma::fragment<wmma::matrix_a, 16, 16, 16, __half, wmma::row_major> ah[2];
            wmma::fragment<wmma::matrix_b, 16, 16, 16, __half, wmma::row_major> bh[4];
#pragma unroll
            for (int mi = 0; mi < 2; ++mi)
                wmma::load_matrix_sync(ah[mi], &Ah[(wm * 32 + mi * 16) * 72 + kk], 72);
#pragma unroll
            for (int ni = 0; ni < 4; ++ni)
                wmma::load_matrix_sync(bh[ni], &Bs[kk * 264 + wd * 64 + ni * 16], 264);
#pragma unroll
            for (int mi = 0; mi < 2; ++mi)
#pragma unroll
                for (int ni = 0; ni < 4; ++ni)
                    wmma::mma_sync(acc[mi][ni], ah[mi], bh[ni], acc[mi][ni]);
        }
        if (pre) {
            G2_WSTORE(ns + (ci + 1) * 64, cur ^ 1, cur ^ 1);
            CP_WAIT0();
        }
        __syncthreads();
    }
    if (tid < 64) {
        int n = ns + (nch - 1) * 64 + tid;
        unsigned v = scm[(nch - 1) & 1][tid];
        if (n < Nn && v) atomicMax(&g_cmax[n], v);
    }

#pragma unroll
    for (int mi = 0; mi < 2; ++mi)
#pragma unroll
        for (int ni = 0; ni < 4; ++ni)
            wmma::store_matrix_sync(&Cs[(wm * 32 + mi * 16) * 264 + wd * 64 + ni * 16],
                                    acc[mi][ni], 264, wmma::mem_row_major);
    __syncthreads();
    const int rr = tid >> 2, cgr = (tid & 3) * 64;
    const size_t ob = ((size_t)sp * B_DIM + m0 + rr) * D_DIM + cgr;
#pragma unroll
    for (int j = 0; j < 64; j += 4)
        *(float4*)&g_part[ob + j] = *(const float4*)&Cs[rr * 264 + cgr + j];
}

// -------------------- reductions / output --------------------------------------
__global__ void reduce_ret_kernel(float* __restrict__ out) {
    size_t i = (size_t)blockIdx.x * 256 + threadIdx.x;
    float4 s = make_float4(0.f, 0.f, 0.f, 0.f);
    for (int sp = 0; sp < NSPLIT; ++sp) {
        float4 v = *(const float4*)&g_part[(size_t)sp * (B_DIM * D_DIM) + i * 4];
        s.x += v.x; s.y += v.y; s.z += v.z; s.w += v.w;
    }
    *(float4*)&out[i * 4] = s;
}

__global__ void depths_kernel(const float* __restrict__ depths,
                              float* __restrict__ out, int Nn) {
    int i = blockIdx.x * 256 + threadIdx.x;
    if (i >= Nn) return;
    float d = depths[i];
    float maxw = __uint_as_float(g_cmax[i]);
    float dom = log1pf(d) / fmaxf(__int_as_float(g_logdmax), 1e-8f);
    float rate = 0.01f * (1.0f - 0.7f * dom);
    out[B_DIM * D_DIM + i] = d + ((maxw > 0.1f) ? rate * maxw : 0.0f);
}

extern "C" void kernel_launch(void* const* d_in, const int* in_sizes, int n_in,
                              void* d_out, int out_size) {
    const float* state  = (const float*)d_in[0];
    const float* W      = (const float*)d_in[1];
    const float* pat    = (const float*)d_in[2];
    const float* depths = (const float*)d_in[3];
    const float* gate   = (const float*)d_in[4];
    float* out = (float*)d_out;
    const int Nn = in_sizes[3];

    cudaFuncSetAttribute(gemm1_kernel, cudaFuncAttributeMaxDynamicSharedMemorySize, SM1_BYTES);
    cudaFuncSetAttribute(gemm2_kernel, cudaFuncAttributeMaxDynamicSharedMemorySize, SM2_BYTES);

    const int nbN = (Nn + 255) / 256;
    init_kernel<<<nbN, 256>>>(Nn);
    proj_kernel<<<B_DIM, 256>>>(state, W);
    bias_kernel<<<nbN, 256>>>(depths, gate, Nn);
    patprep_kernel<<<(NPAD * D_DIM / 4) / 256, 256>>>(pat, Nn);

    gemm1_kernel<<<dim3(B_DIM / 128, NT1), 256, SM1_BYTES>>>(Nn);
    lse_merge_kernel<<<B_DIM / 256, 256>>>(NT1);

    const int CHv = ((Nn + NSPLIT * 64 - 1) / (NSPLIT * 64)) * 64;
    gemm2_kernel<<<dim3(B_DIM / 64, NSPLIT), 256, SM2_BYTES>>>(Nn, CHv);

    reduce_ret_kernel<<<(B_DIM * D_DIM / 4) / 256, 256>>>(out);
    depths_kernel<<<nbN, 256>>>(depths, out, Nn);
}

// round 13
// speedup vs baseline: 1.2252x; 1.0129x over previous
#include <cuda_runtime.h>
#include <cuda_fp16.h>
#include <mma.h>
#include <math.h>
#include <stdint.h>

using namespace nvcuda;

#define B_DIM 1024
#define D_DIM 256
#define NPAD  100352
#define NSPLIT 37
#define NT1 784            // NPAD / 128

__device__ __half g_projh[B_DIM * D_DIM];
__device__ float g_bias[NPAD];
__device__ __half g_e16[(size_t)B_DIM * NPAD];   // exp(z - pm_tile), fp16
__device__ float g_L[B_DIM];
__device__ float g_pm[(size_t)NT1 * B_DIM];
__device__ float g_ps[(size_t)NT1 * B_DIM];
__device__ __half g_patf[(size_t)NPAD * D_DIM];
__device__ float g_part[(size_t)NSPLIT * B_DIM * D_DIM];
__device__ unsigned g_cmax[NPAD];
__device__ int g_logdmax;

// fast exp on FMA pipe (rel err ~3e-6)
__device__ __forceinline__ float fexp(float x) {
    float y = fmaxf(x * 1.44269504088896f, -126.0f);
    float k = rintf(y);
    float f = y - k;
    float p = 1.3333558146e-3f;
    p = fmaf(p, f, 9.6181291076e-3f);
    p = fmaf(p, f, 5.5504108664e-2f);
    p = fmaf(p, f, 2.4022650696e-1f);
    p = fmaf(p, f, 6.9314718056e-1f);
    p = fmaf(p, f, 1.0f);
    return p * __int_as_float(((int)k + 127) << 23);
}
__device__ __forceinline__ uint32_t pk2h(float lo, float hi) {
    uint32_t d; asm("cvt.rn.f16x2.f32 %0, %1, %2;" : "=r"(d) : "f"(hi), "f"(lo)); return d;
}
__device__ __forceinline__ uint32_t smem_u32(const void* p) {
    uint32_t a;
    asm("{ .reg .u64 t; cvta.to.shared.u64 t, %1; cvt.u32.u64 %0, t; }" : "=r"(a) : "l"(p));
    return a;
}
#define CP16(dst, src) \
    asm volatile("cp.async.cg.shared.global [%0], [%1], 16;" :: "r"(dst), "l"(src))
#define CP_COMMIT() asm volatile("cp.async.commit_group;" ::: "memory")
#define CP_WAIT0()  asm volatile("cp.async.wait_group 0;" ::: "memory")

// -------------------- prep ----------------------------------------------------
__global__ void init_kernel(int Nn) {
    int i = blockIdx.x * blockDim.x + threadIdx.x;
    if (i < Nn) g_cmax[i] = 0u;
    if (i == 0) g_logdmax = 0;
}

__global__ void proj_kernel(const float* __restrict__ state, const float* __restrict__ W) {
    __shared__ float s[D_DIM];
    int b = blockIdx.x, j = threadIdx.x;
    s[j] = state[b * D_DIM + j];
    __syncthreads();
    const float* wr = W + j * D_DIM;
    float acc = 0.f;
#pragma unroll 16
    for (int d = 0; d < D_DIM; ++d) acc = fmaf(s[d], wr[d], acc);
    g_projh[b * D_DIM + j] = __float2half_rn(acc);
}

__global__ void bias_kernel(const float* __restrict__ depths,
                            const float* __restrict__ gate, int Nn) {
    int i = blockIdx.x * 256 + threadIdx.x;
    float lv = 0.f;
    if (i < Nn) {
        float d = depths[i], g = gate[i];
        g_bias[i] = logf(fmaxf(d, 1e-8f)) + logf(fmaxf(g, 1e-8f));
        lv = log1pf(d);
    }
    __shared__ float red[256];
    red[threadIdx.x] = lv;
    __syncthreads();
#pragma unroll
    for (int o = 128; o > 0; o >>= 1) {
        if (threadIdx.x < o) red[threadIdx.x] = fmaxf(red[threadIdx.x], red[threadIdx.x + o]);
        __syncthreads();
    }
    if (threadIdx.x == 0) atomicMax(&g_logdmax, __float_as_int(red[0]));
}

__global__ void patprep_kernel(const float* __restrict__ pat, int Nn) {
    long i = (long)blockIdx.x * 256 + threadIdx.x;
    long e0 = i * 4;
    long n = e0 >> 8;
    float4 v = (n < Nn) ? *(const float4*)&pat[e0] : make_float4(0.f, 0.f, 0.f, 0.f);
    *(uint2*)&g_patf[e0] = make_uint2(pk2h(v.x, v.y), pk2h(v.z, v.w));
}

// -------------------- gemm1: e16 = exp(z - pm_tile), z = proj@pat^T + bias ----
// CTA tile 128(M) x 128(N), 8 warps (4x2 of 32x64), k-chunks 64, double buffer.
// smem/stage: A[128][72]h 18432 + B[128][72]h 18432 = 36864; x2 = 73728
// epilogue overlay: float Cs[128][136] = 69632  -> 2 CTAs/SM (reg-lean inner loop)
#define SM1_BYTES 73728
#define G1_STAGE 36864
__global__ __launch_bounds__(256, 2) void gemm1_kernel(int Nn) {
    extern __shared__ char sm[];
    const uint32_t sb = smem_u32(sm);
    float* Cs = (float*)sm;
    const int tid = threadIdx.x, wid = tid >> 5;
    const int wm = wid >> 1, wn = wid & 1;              // 4 x 2 warps, tile 32 x 64
    const int m0 = blockIdx.x * 128;
    const long n0 = (long)blockIdx.y * 128;

    wmma::fragment<wmma::accumulator, 16, 16, 16, float> acc[2][4];
#pragma unroll
    for (int mi = 0; mi < 2; ++mi)
#pragma unroll
        for (int ni = 0; ni < 4; ++ni) wmma::fill_fragment(acc[mi][ni], 0.0f);

    const int ar = tid >> 1, ac = (tid & 1) * 32;       // 64B per thread per operand
    const char* sA = (const char*)(g_projh + (size_t)(m0 + ar) * D_DIM + ac);
    const char* sB = (const char*)(g_patf + (n0 + ar) * D_DIM + ac);
    const uint32_t dA = sb + ar * 144 + ac * 2;
    const uint32_t dB = sb + 18432 + ar * 144 + ac * 2;

#define G1_ISSUE(c, buf) do { \
        long ob = (long)(c) * 128; \
        uint32_t da = dA + (buf) * G1_STAGE, db = dB + (buf) * G1_STAGE; \
        CP16(da, sA + ob); CP16(da + 16, sA + ob + 16); \
        CP16(da + 32, sA + ob + 32); CP16(da + 48, sA + ob + 48); \
        CP16(db, sB + ob); CP16(db + 16, sB + ob + 16); \
        CP16(db + 32, sB + ob + 32); CP16(db + 48, sB + ob + 48); \
        CP_COMMIT(); } while (0)

    G1_ISSUE(0, 0);
    CP_WAIT0();
    __syncthreads();

    for (int c = 0; c < 4; ++c) {
        const int cur = c & 1;
        if (c < 3) G1_ISSUE(c + 1, cur ^ 1);
        const __half* Ah = (const __half*)(sm + cur * G1_STAGE);
        const __half* Bs = (const __half*)(sm + cur * G1_STAGE + 18432);
#pragma unroll
        for (int kk = 0; kk < 64; kk += 16) {
            wmma::fragment<wmma::matrix_a, 16, 16, 16, __half, wmma::row_major> ah[2];
#pragma unroll
            for (int mi = 0; mi < 2; ++mi)
                wmma::load_matrix_sync(ah[mi], &Ah[(wm * 32 + mi * 16) * 72 + kk], 72);
#pragma unroll
            for (int ni = 0; ni < 4; ++ni) {
                wmma::fragment<wmma::matrix_b, 16, 16, 16, __half, wmma::col_major> bh;
                wmma::load_matrix_sync(bh, &Bs[(wn * 64 + ni * 16) * 72 + kk], 72);
                wmma::mma_sync(acc[0][ni], ah[0], bh, acc[0][ni]);
                wmma::mma_sync(acc[1][ni], ah[1], bh, acc[1][ni]);
            }
        }
        if (c < 3) CP_WAIT0();
        __syncthreads();
    }

#pragma unroll
    for (int mi = 0; mi < 2; ++mi)
#pragma unroll
        for (int ni = 0; ni < 4; ++ni)
            wmma::store_matrix_sync(&Cs[(wm * 32 + mi * 16) * 136 + wn * 64 + ni * 16],
                                    acc[mi][ni], 136, wmma::mem_row_major);
    __syncthreads();

    // epilogue: pm = row-tile max of (c + bias); e16 = exp(z - pm); sum; store fp16
    const int r2 = tid >> 1, hc = (tid & 1) * 64;
    const int m = m0 + r2;
    const float* crow = Cs + r2 * 136 + hc;
    float vmax = -3.0e38f;
#pragma unroll
    for (int j = 0; j < 64; j += 4) {
        long n = n0 + hc + j;
        if (n + 4 <= Nn) {
            float4 b4 = *(const float4*)&g_bias[n];
            float4 c4 = *(const float4*)&crow[j];
            vmax = fmaxf(vmax, fmaxf(fmaxf(c4.x + b4.x, c4.y + b4.y),
                                     fmaxf(c4.z + b4.z, c4.w + b4.w)));
        } else {
            for (int q = 0; q < 4; ++q)
                if (n + q < Nn) vmax = fmaxf(vmax, crow[j + q] + g_bias[n + q]);
        }
    }
    float pmv = fmaxf(vmax, __shfl_xor_sync(0xffffffffu, vmax, 1));

    float s = 0.f;
    __half* erow = g_e16 + (size_t)m * NPAD + n0 + hc;
#pragma unroll
    for (int j = 0; j < 64; j += 8) {
        long n = n0 + hc + j;
        uint32_t hh[4];
        if (n + 8 <= Nn) {
            float4 ba = *(const float4*)&g_bias[n];
            float4 ca = *(const float4*)&crow[j];
            float4 bb = *(const float4*)&g_bias[n + 4];
            float4 cb = *(const float4*)&crow[j + 4];
            float e0 = fexp(ca.x + ba.x - pmv), e1 = fexp(ca.y + ba.y - pmv);
            float e2 = fexp(ca.z + ba.z - pmv), e3 = fexp(ca.w + ba.w - pmv);
            float e4 = fexp(cb.x + bb.x - pmv), e5 = fexp(cb.y + bb.y - pmv);
            float e6 = fexp(cb.z + bb.z - pmv), e7 = fexp(cb.w + bb.w - pmv);
            s += (e0 + e1) + (e2 + e3) + (e4 + e5) + (e6 + e7);
            hh[0] = pk2h(e0, e1); hh[1] = pk2h(e2, e3);
            hh[2] = pk2h(e4, e5); hh[3] = pk2h(e6, e7);
        } else {
            float e[8];
            for (int q = 0; q < 8; ++q) {
                long nn = n + q;
                e[q] = (nn < Nn) ? fexp(crow[j + q] + g_bias[nn] - pmv) : 0.f;
                s += e[q];
            }
            hh[0] = pk2h(e[0], e[1]); hh[1] = pk2h(e[2], e[3]);
            hh[2] = pk2h(e[4], e[5]); hh[3] = pk2h(e[6], e[7]);
        }
        *(uint4*)&erow[j] = make_uint4(hh[0], hh[1], hh[2], hh[3]);
    }
    s += __shfl_xor_sync(0xffffffffu, s, 1);
    if ((tid & 1) == 0) {
        g_pm[(size_t)blockIdx.y * B_DIM + m] = pmv;
        g_ps[(size_t)blockIdx.y * B_DIM + m] = s;
    }
}

// -------------------- lse merge -------------------------------------------------
__global__ void lse_merge_kernel(int ntiles) {
    int m = blockIdx.x * 256 + threadIdx.x;
    if (m >= B_DIM) return;
    float M = -3.0e38f;
    for (int t = 0; t < ntiles; ++t) M = fmaxf(M, g_pm[(size_t)t * B_DIM + m]);
    float S = 0.f;
    for (int t = 0; t < ntiles; ++t) {
        float pm = g_pm[(size_t)t * B_DIM + m];
        if (pm > -1.0e38f) S += g_ps[(size_t)t * B_DIM + m] * fexp(pm - M);
    }
    g_L[m] = M + logf(S);
}

// -------------------- gemm2: part = (e16 * s_tile) @ pat + colmax ---------------
// CTA tile 64(M) x 256(D), 8 warps (2x4 of 32x64), k-chunk 64, double buffer.
// smem/stage: A[64][72]h 9216 + B[64][264]h 33792 = 43008; x2 = 86016 -> 2 CTAs/SM
// epilogue overlay: float Cs[64][264] = 67584   (reg-lean inner loop)
#define SM2_BYTES 86016
#define G2_STAGE 43008
__global__ __launch_bounds__(256, 2) void gemm2_kernel(int Nn, int CHv) {
    extern __shared__ char sm[];
    const uint32_t sb = smem_u32(sm);
    float* Cs = (float*)sm;
    __shared__ unsigned scm[2][64];
    const int tid = threadIdx.x, wid = tid >> 5, lane = tid & 31;
    const int wm = wid >> 2, wd = wid & 3;              // 2 x 4 warps, tile 32 x 64
    const int m0 = blockIdx.x * 64;
    const int sp = blockIdx.y;
    const int ns = sp * CHv, ne = min(ns + CHv, Nn);
    if (ns >= ne) {
        const size_t pb = ((size_t)sp * B_DIM + m0) * D_DIM;
        for (int i = tid; i < 64 * D_DIM / 4; i += 256)
            *(float4*)&g_part[pb + (size_t)i * 4] = make_float4(0.f, 0.f, 0.f, 0.f);
        return;
    }
    const int nch = (ne - ns + 63) / 64;

    wmma::fragment<wmma::accumulator, 16, 16, 16, float> acc[2][4];
#pragma unroll
    for (int mi = 0; mi < 2; ++mi)
#pragma unroll
        for (int ni = 0; ni < 4; ++ni) wmma::fill_fragment(acc[mi][ni], 0.0f);

    const int r = tid >> 2, ng = (tid & 3) * 16;
    const float Lm = g_L[m0 + r];
    const __half* erow = g_e16 + (size_t)(m0 + r) * NPAD;
    const uint32_t dA = sb + r * 144 + ng * 2;
    if (tid < 64) { scm[0][tid] = 0u; scm[1][tid] = 0u; }
    __syncthreads();

    uint32_t ev[8];   // 16 fp16 e-values

#define G2_ZLOAD(k0v) do { \
        long nbase = (long)(k0v) + ng; \
        *(uint4*)&ev[0] = *(const uint4*)&erow[nbase]; \
        *(uint4*)&ev[4] = *(const uint4*)&erow[nbase + 8]; \
    } while (0)

#define G2_WSTORE(k0v, buf, chpar) do { \
        int t = (int)((k0v) >> 7); \
        float sfac = fexp(g_pm[(size_t)t * B_DIM + m0 + r] - Lm); \
        __half2 sh2 = __float2half2_rn(sfac); \
        uint32_t h2v[8]; \
        float w[16]; \
        for (int j = 0; j < 8; ++j) { \
            __half2 a = *reinterpret_cast<__half2*>(&ev[j]); \
            __half2 pr = __hmul2(a, sh2); \
            h2v[j] = *reinterpret_cast<uint32_t*>(&pr); \
            float2 f = __half22float2(pr); \
            w[2 * j] = f.x; w[2 * j + 1] = f.y; \
        } \
        uint32_t doff = dA + (buf) * G2_STAGE - sb; \
        *(uint4*)(sm + doff) = make_uint4(h2v[0], h2v[1], h2v[2], h2v[3]); \
        *(uint4*)(sm + doff + 16) = make_uint4(h2v[4], h2v[5], h2v[6], h2v[7]); \
        uint32_t cm[16]; \
        for (int j = 0; j < 16; ++j) cm[j] = __float_as_uint(w[j]); \
        for (int off = 4; off <= 16; off <<= 1) \
            for (int j = 0; j < 16; ++j) { \
                uint32_t o = __shfl_xor_sync(0xffffffffu, cm[j], off); \
                cm[j] = (o > cm[j]) ? o : cm[j]; \
            } \
        if (lane < 4) \
            for (int j = 0; j < 16; ++j) atomicMax(&scm[chpar][lane * 16 + j], cm[j]); \
    } while (0)

#define G2_BISSUE(k0v, buf) do { \
        uint32_t base = sb + (buf) * G2_STAGE + 9216; \
        const char* psrc = (const char*)(g_patf + (size_t)(k0v) * D_DIM); \
        for (int k = 0; k < 8; ++k) { \
            int s0 = tid + k * 256; \
            CP16(base + (s0 >> 5) * 528 + (s0 & 31) * 16, psrc + (s0 >> 5) * 512 + (s0 & 31) * 16); \
        } \
        CP_COMMIT(); } while (0)

    G2_BISSUE(ns, 0);
    G2_ZLOAD(ns);
    G2_WSTORE(ns, 0, 0);
    CP_WAIT0();
    __syncthreads();

    for (int ci = 0; ci < nch; ++ci) {
        const int cur = ci & 1;
        if (ci > 0 && tid < 64) {
            int n = ns + (ci - 1) * 64 + tid;
            unsigned v = scm[cur ^ 1][tid];
            if (n < Nn && v) atomicMax(&g_cmax[n], v);
            scm[cur ^ 1][tid] = 0u;
        }
        const bool pre = (ci + 1 < nch);
        if (pre) {
            G2_BISSUE(ns + (ci + 1) * 64, cur ^ 1);
            G2_ZLOAD(ns + (ci + 1) * 64);       // prefetch e16 under MMA
        }

        const __half* Ah = (const __half*)(sm + cur * G2_STAGE);
        const __half* Bs = (const __half*)(sm + cur * G2_STAGE + 9216);
#pragma unroll
        for (int kk = 0; kk < 64; kk += 16) {
            wmma::fragment<wmma::matrix_a, 16, 16, 16, __half, wmma::row_major> ah[2];
#pragma unroll
            for (int mi = 0; mi < 2; ++mi)
                wmma::load_matrix_sync(ah[mi], &Ah[(wm * 32 + mi * 16) * 72 + kk], 72);
#pragma unroll
            for (int ni = 0; ni < 4; ++ni) {
                wmma::fragment<wmma::matrix_b, 16, 16, 16, __half, wmma::row_major> bh;
                wmma::load_matrix_sync(bh, &Bs[kk * 264 + wd * 64 + ni * 16], 264);
                wmma::mma_sync(acc[0][ni], ah[0], bh, acc[0][ni]);
                wmma::mma_sync(acc[1][ni], ah[1], bh, acc[1][ni]);
            }
        }
        if (pre) {
            G2_WSTORE(ns + (ci + 1) * 64, cur ^ 1, cur ^ 1);
            CP_WAIT0();
        }
        __syncthreads();
    }
    if (tid < 64) {
        int n = ns + (nch - 1) * 64 + tid;
        unsigned v = scm[(nch - 1) & 1][tid];
        if (n < Nn && v) atomicMax(&g_cmax[n], v);
    }

#pragma unroll
    for (int mi = 0; mi < 2; ++mi)
#pragma unroll
        for (int ni = 0; ni < 4; ++ni)
            wmma::store_matrix_sync(&Cs[(wm * 32 + mi * 16) * 264 + wd * 64 + ni * 16],
                                    acc[mi][ni], 264, wmma::mem_row_major);
    __syncthreads();
    const int rr = tid >> 2, cgr = (tid & 3) * 64;
    const size_t ob = ((size_t)sp * B_DIM + m0 + rr) * D_DIM + cgr;
#pragma unroll
    for (int j = 0; j < 64; j += 4)
        *(float4*)&g_part[ob + j] = *(const float4*)&Cs[rr * 264 + cgr + j];
}

// -------------------- reductions / output --------------------------------------
__global__ void reduce_ret_kernel(float* __restrict__ out) {
    size_t i = (size_t)blockIdx.x * 256 + threadIdx.x;
    float4 s = make_float4(0.f, 0.f, 0.f, 0.f);
    for (int sp = 0; sp < NSPLIT; ++sp) {
        float4 v = *(const float4*)&g_part[(size_t)sp * (B_DIM * D_DIM) + i * 4];
        s.x += v.x; s.y += v.y; s.z += v.z; s.w += v.w;
    }
    *(float4*)&out[i * 4] = s;
}

__global__ void depths_kernel(const float* __restrict__ depths,
                              float* __restrict__ out, int Nn) {
    int i = blockIdx.x * 256 + threadIdx.x;
    if (i >= Nn) return;
    float d = depths[i];
    float maxw = __uint_as_float(g_cmax[i]);
    float dom = log1pf(d) / fmaxf(__int_as_float(g_logdmax), 1e-8f);
    float rate = 0.01f * (1.0f - 0.7f * dom);
    out[B_DIM * D_DIM + i] = d + ((maxw > 0.1f) ? rate * maxw : 0.0f);
}

extern "C" void kernel_launch(void* const* d_in, const int* in_sizes, int n_in,
                              void* d_out, int out_size) {
    const float* state  = (const float*)d_in[0];
    const float* W      = (const float*)d_in[1];
    const float* pat    = (const float*)d_in[2];
    const float* depths = (const float*)d_in[3];
    const float* gate   = (const float*)d_in[4];
    float* out = (float*)d_out;
    const int Nn = in_sizes[3];

    cudaFuncSetAttribute(gemm1_kernel, cudaFuncAttributeMaxDynamicSharedMemorySize, SM1_BYTES);
    cudaFuncSetAttribute(gemm2_kernel, cudaFuncAttributeMaxDynamicSharedMemorySize, SM2_BYTES);

    const int nbN = (Nn + 255) / 256;
    init_kernel<<<nbN, 256>>>(Nn);
    proj_kernel<<<B_DIM, 256>>>(state, W);
    bias_kernel<<<nbN, 256>>>(depths, gate, Nn);
    patprep_kernel<<<(NPAD * D_DIM / 4) / 256, 256>>>(pat, Nn);

    gemm1_kernel<<<dim3(B_DIM / 128, NT1), 256, SM1_BYTES>>>(Nn);
    lse_merge_kernel<<<B_DIM / 256, 256>>>(NT1);

    const int CHv = ((Nn + NSPLIT * 64 - 1) / (NSPLIT * 64)) * 64;
    gemm2_kernel<<<dim3(B_DIM / 64, NSPLIT), 256, SM2_BYTES>>>(Nn, CHv);

    reduce_ret_kernel<<<(B_DIM * D_DIM / 4) / 256, 256>>>(out);
    depths_kernel<<<nbN, 256>>>(depths, out, Nn);
}

// round 14
// speedup vs baseline: 1.2501x; 1.0203x over previous
#include <cuda_runtime.h>
#include <cuda_fp16.h>
#include <mma.h>
#include <math.h>
#include <stdint.h>

using namespace nvcuda;

#define B_DIM 1024
#define D_DIM 256
#define NPAD  100352
#define NSPLIT 37
#define NT1 784            // NPAD / 128

__device__ __half g_projh[B_DIM * D_DIM];
__device__ float g_bias[NPAD];
__device__ __half g_e16[(size_t)B_DIM * NPAD];   // exp(z - pm_tile), fp16
__device__ float g_L[B_DIM];
__device__ float g_pm[(size_t)NT1 * B_DIM];
__device__ float g_ps[(size_t)NT1 * B_DIM];
__device__ __half g_patf[(size_t)NPAD * D_DIM];
__device__ float g_part[(size_t)NSPLIT * B_DIM * D_DIM];
__device__ unsigned g_cmax[NPAD];
__device__ int g_logdmax;

// fast exp on FMA pipe (rel err ~3e-6)
__device__ __forceinline__ float fexp(float x) {
    float y = fmaxf(x * 1.44269504088896f, -126.0f);
    float k = rintf(y);
    float f = y - k;
    float p = 1.3333558146e-3f;
    p = fmaf(p, f, 9.6181291076e-3f);
    p = fmaf(p, f, 5.5504108664e-2f);
    p = fmaf(p, f, 2.4022650696e-1f);
    p = fmaf(p, f, 6.9314718056e-1f);
    p = fmaf(p, f, 1.0f);
    return p * __int_as_float(((int)k + 127) << 23);
}
__device__ __forceinline__ uint32_t pk2h(float lo, float hi) {
    uint32_t d; asm("cvt.rn.f16x2.f32 %0, %1, %2;" : "=r"(d) : "f"(hi), "f"(lo)); return d;
}
__device__ __forceinline__ uint32_t smem_u32(const void* p) {
    uint32_t a;
    asm("{ .reg .u64 t; cvta.to.shared.u64 t, %1; cvt.u32.u64 %0, t; }" : "=r"(a) : "l"(p));
    return a;
}
#define CP16(dst, src) \
    asm volatile("cp.async.cg.shared.global [%0], [%1], 16;" :: "r"(dst), "l"(src))
#define CP_COMMIT() asm volatile("cp.async.commit_group;" ::: "memory")
#define CP_WAIT0()  asm volatile("cp.async.wait_group 0;" ::: "memory")

// -------------------- prep ----------------------------------------------------
__global__ void proj_kernel(const float* __restrict__ state, const float* __restrict__ W) {
    __shared__ float s[D_DIM];
    int b = blockIdx.x, j = threadIdx.x;
    s[j] = state[b * D_DIM + j];
    __syncthreads();
    const float* wr = W + j * D_DIM;
    float acc = 0.f;
#pragma unroll 16
    for (int d = 0; d < D_DIM; ++d) acc = fmaf(s[d], wr[d], acc);
    g_projh[b * D_DIM + j] = __float2half_rn(acc);
}

// patprep also performs init (zero cmax / logdmax); runs BEFORE bias_kernel.
__global__ void patprep_kernel(const float* __restrict__ pat, int Nn) {
    long i = (long)blockIdx.x * 256 + threadIdx.x;
    if (i < Nn) g_cmax[i] = 0u;
    if (i == 0) g_logdmax = 0;
    long e0 = i * 4;
    long n = e0 >> 8;
    float4 v = (n < Nn) ? *(const float4*)&pat[e0] : make_float4(0.f, 0.f, 0.f, 0.f);
    *(uint2*)&g_patf[e0] = make_uint2(pk2h(v.x, v.y), pk2h(v.z, v.w));
}

__global__ void bias_kernel(const float* __restrict__ depths,
                            const float* __restrict__ gate, int Nn) {
    int i = blockIdx.x * 256 + threadIdx.x;
    float lv = 0.f;
    if (i < Nn) {
        float d = depths[i], g = gate[i];
        g_bias[i] = logf(fmaxf(d, 1e-8f)) + logf(fmaxf(g, 1e-8f));
        lv = log1pf(d);
    }
    __shared__ float red[256];
    red[threadIdx.x] = lv;
    __syncthreads();
#pragma unroll
    for (int o = 128; o > 0; o >>= 1) {
        if (threadIdx.x < o) red[threadIdx.x] = fmaxf(red[threadIdx.x], red[threadIdx.x + o]);
        __syncthreads();
    }
    if (threadIdx.x == 0) atomicMax(&g_logdmax, __float_as_int(red[0]));
}

// -------------------- gemm1: e16 = exp(z - pm_tile), z = proj@pat^T + bias ----
// CTA tile 128(M) x 128(N), 8 warps (4x2 of 32x64), k-chunks 64, double buffer.
// smem/stage: A[128][72]h 18432 + B[128][72]h 18432 = 36864; x2 = 73728
// epilogue overlay: float Cs[128][136] = 69632  -> 2 CTAs/SM (reg-lean inner loop)
#define SM1_BYTES 73728
#define G1_STAGE 36864
__global__ __launch_bounds__(256, 2) void gemm1_kernel(int Nn) {
    extern __shared__ char sm[];
    const uint32_t sb = smem_u32(sm);
    float* Cs = (float*)sm;
    const int tid = threadIdx.x, wid = tid >> 5;
    const int wm = wid >> 1, wn = wid & 1;              // 4 x 2 warps, tile 32 x 64
    const int m0 = blockIdx.x * 128;
    const long n0 = (long)blockIdx.y * 128;

    wmma::fragment<wmma::accumulator, 16, 16, 16, float> acc[2][4];
#pragma unroll
    for (int mi = 0; mi < 2; ++mi)
#pragma unroll
        for (int ni = 0; ni < 4; ++ni) wmma::fill_fragment(acc[mi][ni], 0.0f);

    const int ar = tid >> 1, ac = (tid & 1) * 32;       // 64B per thread per operand
    const char* sA = (const char*)(g_projh + (size_t)(m0 + ar) * D_DIM + ac);
    const char* sB = (const char*)(g_patf + (n0 + ar) * D_DIM + ac);
    const uint32_t dA = sb + ar * 144 + ac * 2;
    const uint32_t dB = sb + 18432 + ar * 144 + ac * 2;

#define G1_ISSUE(c, buf) do { \
        long ob = (long)(c) * 128; \
        uint32_t da = dA + (buf) * G1_STAGE, db = dB + (buf) * G1_STAGE; \
        CP16(da, sA + ob); CP16(da + 16, sA + ob + 16); \
        CP16(da + 32, sA + ob + 32); CP16(da + 48, sA + ob + 48); \
        CP16(db, sB + ob); CP16(db + 16, sB + ob + 16); \
        CP16(db + 32, sB + ob + 32); CP16(db + 48, sB + ob + 48); \
        CP_COMMIT(); } while (0)

    G1_ISSUE(0, 0);
    CP_WAIT0();
    __syncthreads();

    for (int c = 0; c < 4; ++c) {
        const int cur = c & 1;
        if (c < 3) G1_ISSUE(c + 1, cur ^ 1);
        const __half* Ah = (const __half*)(sm + cur * G1_STAGE);
        const __half* Bs = (const __half*)(sm + cur * G1_STAGE + 18432);
#pragma unroll
        for (int kk = 0; kk < 64; kk += 16) {
            wmma::fragment<wmma::matrix_a, 16, 16, 16, __half, wmma::row_major> ah[2];
#pragma unroll
            for (int mi = 0; mi < 2; ++mi)
                wmma::load_matrix_sync(ah[mi], &Ah[(wm * 32 + mi * 16) * 72 + kk], 72);
#pragma unroll
            for (int ni = 0; ni < 4; ++ni) {
                wmma::fragment<wmma::matrix_b, 16, 16, 16, __half, wmma::col_major> bh;
                wmma::load_matrix_sync(bh, &Bs[(wn * 64 + ni * 16) * 72 + kk], 72);
                wmma::mma_sync(acc[0][ni], ah[0], bh, acc[0][ni]);
                wmma::mma_sync(acc[1][ni], ah[1], bh, acc[1][ni]);
            }
        }
        if (c < 3) CP_WAIT0();
        __syncthreads();
    }

#pragma unroll
    for (int mi = 0; mi < 2; ++mi)
#pragma unroll
        for (int ni = 0; ni < 4; ++ni)
            wmma::store_matrix_sync(&Cs[(wm * 32 + mi * 16) * 136 + wn * 64 + ni * 16],
                                    acc[mi][ni], 136, wmma::mem_row_major);
    __syncthreads();

    // epilogue: pm = row-tile max of (c + bias); e16 = exp(z - pm); sum; store fp16
    const int r2 = tid >> 1, hc = (tid & 1) * 64;
    const int m = m0 + r2;
    const float* crow = Cs + r2 * 136 + hc;
    float vmax = -3.0e38f;
#pragma unroll
    for (int j = 0; j < 64; j += 4) {
        long n = n0 + hc + j;
        if (n + 4 <= Nn) {
            float4 b4 = *(const float4*)&g_bias[n];
            float4 c4 = *(const float4*)&crow[j];
            vmax = fmaxf(vmax, fmaxf(fmaxf(c4.x + b4.x, c4.y + b4.y),
                                     fmaxf(c4.z + b4.z, c4.w + b4.w)));
        } else {
            for (int q = 0; q < 4; ++q)
                if (n + q < Nn) vmax = fmaxf(vmax, crow[j + q] + g_bias[n + q]);
        }
    }
    float pmv = fmaxf(vmax, __shfl_xor_sync(0xffffffffu, vmax, 1));

    float s = 0.f;
    __half* erow = g_e16 + (size_t)m * NPAD + n0 + hc;
#pragma unroll
    for (int j = 0; j < 64; j += 8) {
        long n = n0 + hc + j;
        uint32_t hh[4];
        if (n + 8 <= Nn) {
            float4 ba = *(const float4*)&g_bias[n];
            float4 ca = *(const float4*)&crow[j];
            float4 bb = *(const float4*)&g_bias[n + 4];
            float4 cb = *(const float4*)&crow[j + 4];
            float e0 = fexp(ca.x + ba.x - pmv), e1 = fexp(ca.y + ba.y - pmv);
            float e2 = fexp(ca.z + ba.z - pmv), e3 = fexp(ca.w + ba.w - pmv);
            float e4 = fexp(cb.x + bb.x - pmv), e5 = fexp(cb.y + bb.y - pmv);
            float e6 = fexp(cb.z + bb.z - pmv), e7 = fexp(cb.w + bb.w - pmv);
            s += (e0 + e1) + (e2 + e3) + (e4 + e5) + (e6 + e7);
            hh[0] = pk2h(e0, e1); hh[1] = pk2h(e2, e3);
            hh[2] = pk2h(e4, e5); hh[3] = pk2h(e6, e7);
        } else {
            float e[8];
            for (int q = 0; q < 8; ++q) {
                long nn = n + q;
                e[q] = (nn < Nn) ? fexp(crow[j + q] + g_bias[nn] - pmv) : 0.f;
                s += e[q];
            }
            hh[0] = pk2h(e[0], e[1]); hh[1] = pk2h(e[2], e[3]);
            hh[2] = pk2h(e[4], e[5]); hh[3] = pk2h(e[6], e[7]);
        }
        *(uint4*)&erow[j] = make_uint4(hh[0], hh[1], hh[2], hh[3]);
    }
    s += __shfl_xor_sync(0xffffffffu, s, 1);
    if ((tid & 1) == 0) {
        g_pm[(size_t)blockIdx.y * B_DIM + m] = pmv;
        g_ps[(size_t)blockIdx.y * B_DIM + m] = s;
    }
}

// -------------------- lse merge -------------------------------------------------
__global__ void lse_merge_kernel(int ntiles) {
    int m = blockIdx.x * 256 + threadIdx.x;
    if (m >= B_DIM) return;
    float M = -3.0e38f;
    for (int t = 0; t < ntiles; ++t) M = fmaxf(M, g_pm[(size_t)t * B_DIM + m]);
    float S = 0.f;
    for (int t = 0; t < ntiles; ++t) {
        float pm = g_pm[(size_t)t * B_DIM + m];
        if (pm > -1.0e38f) S += g_ps[(size_t)t * B_DIM + m] * fexp(pm - M);
    }
    g_L[m] = M + logf(S);
}

// -------------------- gemm2: part = (e16 * s_tile) @ pat + colmax ---------------
// CTA tile 64(M) x 256(D), 8 warps (2x4 of 32x64), k-chunk 64, double buffer.
// smem/stage: A[64][72]h 9216 + B[64][264]h 33792 = 43008; x2 = 86016 -> 2 CTAs/SM
// epilogue overlay: float Cs[64][264] = 67584   (reg-lean inner loop)
#define SM2_BYTES 86016
#define G2_STAGE 43008
__global__ __launch_bounds__(256, 2) void gemm2_kernel(int Nn, int CHv) {
    extern __shared__ char sm[];
    const uint32_t sb = smem_u32(sm);
    float* Cs = (float*)sm;
    __shared__ unsigned scm[2][64];
    const int tid = threadIdx.x, wid = tid >> 5, lane = tid & 31;
    const int wm = wid >> 2, wd = wid & 3;              // 2 x 4 warps, tile 32 x 64
    const int m0 = blockIdx.x * 64;
    const int sp = blockIdx.y;
    const int ns = sp * CHv, ne = min(ns + CHv, Nn);
    if (ns >= ne) {
        const size_t pb = ((size_t)sp * B_DIM + m0) * D_DIM;
        for (int i = tid; i < 64 * D_DIM / 4; i += 256)
            *(float4*)&g_part[pb + (size_t)i * 4] = make_float4(0.f, 0.f, 0.f, 0.f);
        return;
    }
    const int nch = (ne - ns + 63) / 64;

    wmma::fragment<wmma::accumulator, 16, 16, 16, float> acc[2][4];
#pragma unroll
    for (int mi = 0; mi < 2; ++mi)
#pragma unroll
        for (int ni = 0; ni < 4; ++ni) wmma::fill_fragment(acc[mi][ni], 0.0f);

    const int r = tid >> 2, ng = (tid & 3) * 16;
    const float Lm = g_L[m0 + r];
    const __half* erow = g_e16 + (size_t)(m0 + r) * NPAD;
    const uint32_t dA = sb + r * 144 + ng * 2;
    if (tid < 64) { scm[0][tid] = 0u; scm[1][tid] = 0u; }
    __syncthreads();

    uint32_t ev[8];   // 16 fp16 e-values

#define G2_ZLOAD(k0v) do { \
        long nbase = (long)(k0v) + ng; \
        *(uint4*)&ev[0] = *(const uint4*)&erow[nbase]; \
        *(uint4*)&ev[4] = *(const uint4*)&erow[nbase + 8]; \
    } while (0)

#define G2_WSTORE(k0v, buf, chpar) do { \
        int t = (int)((k0v) >> 7); \
        float sfac = fexp(g_pm[(size_t)t * B_DIM + m0 + r] - Lm); \
        __half2 sh2 = __float2half2_rn(sfac); \
        __half2 pr[8]; \
        for (int j = 0; j < 8; ++j) \
            pr[j] = __hmul2(*reinterpret_cast<__half2*>(&ev[j]), sh2); \
        uint32_t doff = dA + (buf) * G2_STAGE - sb; \
        *(uint4*)(sm + doff) = *(uint4*)&pr[0]; \
        *(uint4*)(sm + doff + 16) = *(uint4*)&pr[4]; \
        __half2 hm[8]; \
        for (int j = 0; j < 8; ++j) hm[j] = pr[j]; \
        for (int off = 4; off <= 16; off <<= 1) \
            for (int j = 0; j < 8; ++j) { \
                __half2 o = __shfl_xor_sync(0xffffffffu, hm[j], off); \
                hm[j] = __hmax2(hm[j], o); \
            } \
        if (lane < 4) \
            for (int j = 0; j < 8; ++j) { \
                float2 f = __half22float2(hm[j]); \
                atomicMax(&scm[chpar][lane * 16 + 2 * j], __float_as_uint(f.x)); \
                atomicMax(&scm[chpar][lane * 16 + 2 * j + 1], __float_as_uint(f.y)); \
            } \
    } while (0)

#define G2_BISSUE(k0v, buf) do { \
        uint32_t base = sb + (buf) * G2_STAGE + 9216; \
        const char* psrc = (const char*)(g_patf + (size_t)(k0v) * D_DIM); \
        for (int k = 0; k < 8; ++k) { \
            int s0 = tid + k * 256; \
            CP16(base + (s0 >> 5) * 528 + (s0 & 31) * 16, psrc + (s0 >> 5) * 512 + (s0 & 31) * 16); \
        } \
        CP_COMMIT(); } while (0)

    G2_BISSUE(ns, 0);
    G2_ZLOAD(ns);
    G2_WSTORE(ns, 0, 0);
    CP_WAIT0();
    __syncthreads();

    for (int ci = 0; ci < nch; ++ci) {
        const int cur = ci & 1;
        if (ci > 0 && tid < 64) {
            int n = ns + (ci - 1) * 64 + tid;
            unsigned v = scm[cur ^ 1][tid];
            if (n < Nn && v) atomicMax(&g_cmax[n], v);
            scm[cur ^ 1][tid] = 0u;
        }
        const bool pre = (ci + 1 < nch);
        if (pre) {
            G2_BISSUE(ns + (ci + 1) * 64, cur ^ 1);
            G2_ZLOAD(ns + (ci + 1) * 64);       // prefetch e16 under MMA
        }

        const __half* Ah = (const __half*)(sm + cur * G2_STAGE);
        const __half* Bs = (const __half*)(sm + cur * G2_STAGE + 9216);
#pragma unroll
        for (int kk = 0; kk < 64; kk += 16) {
            wmma::fragment<wmma::matrix_a, 16, 16, 16, __half, wmma::row_major> ah[2];
#pragma unroll
            for (int mi = 0; mi < 2; ++mi)
                wmma::load_matrix_sync(ah[mi], &Ah[(wm * 32 + mi * 16) * 72 + kk], 72);
#pragma unroll
            for (int ni = 0; ni < 4; ++ni) {
                wmma::fragment<wmma::matrix_b, 16, 16, 16, __half, wmma::row_major> bh;
                wmma::load_matrix_sync(bh, &Bs[kk * 264 + wd * 64 + ni * 16], 264);
                wmma::mma_sync(acc[0][ni], ah[0], bh, acc[0][ni]);
                wmma::mma_sync(acc[1][ni], ah[1], bh, acc[1][ni]);
            }
        }
        if (pre) {
            G2_WSTORE(ns + (ci + 1) * 64, cur ^ 1, cur ^ 1);
            CP_WAIT0();
        }
        __syncthreads();
    }
    if (tid < 64) {
        int n = ns + (nch - 1) * 64 + tid;
        unsigned v = scm[(nch - 1) & 1][tid];
        if (n < Nn && v) atomicMax(&g_cmax[n], v);
    }

#pragma unroll
    for (int mi = 0; mi < 2; ++mi)
#pragma unroll
        for (int ni = 0; ni < 4; ++ni)
            wmma::store_matrix_sync(&Cs[(wm * 32 + mi * 16) * 264 + wd * 64 + ni * 16],
                                    acc[mi][ni], 264, wmma::mem_row_major);
    __syncthreads();
    const int rr = tid >> 2, cgr = (tid & 3) * 64;
    const size_t ob = ((size_t)sp * B_DIM + m0 + rr) * D_DIM + cgr;
#pragma unroll
    for (int j = 0; j < 64; j += 4)
        *(float4*)&g_part[ob + j] = *(const float4*)&Cs[rr * 264 + cgr + j];
}

// -------------------- reductions / output --------------------------------------
__global__ void reduce_ret_kernel(float* __restrict__ out) {
    size_t i = (size_t)blockIdx.x * 256 + threadIdx.x;
    float4 s = make_float4(0.f, 0.f, 0.f, 0.f);
    for (int sp = 0; sp < NSPLIT; ++sp) {
        float4 v = *(const float4*)&g_part[(size_t)sp * (B_DIM * D_DIM) + i * 4];
        s.x += v.x; s.y += v.y; s.z += v.z; s.w += v.w;
    }
    *(float4*)&out[i * 4] = s;
}

__global__ void depths_kernel(const float* __restrict__ depths,
                              float* __restrict__ out, int Nn) {
    int i = blockIdx.x * 256 + threadIdx.x;
    if (i >= Nn) return;
    float d = depths[i];
    float maxw = __uint_as_float(g_cmax[i]);
    float dom = log1pf(d) / fmaxf(__int_as_float(g_logdmax), 1e-8f);
    float rate = 0.01f * (1.0f - 0.7f * dom);
    out[B_DIM * D_DIM + i] = d + ((maxw > 0.1f) ? rate * maxw : 0.0f);
}

extern "C" void kernel_launch(void* const* d_in, const int* in_sizes, int n_in,
                              void* d_out, int out_size) {
    const float* state  = (const float*)d_in[0];
    const float* W      = (const float*)d_in[1];
    const float* pat    = (const float*)d_in[2];
    const float* depths = (const float*)d_in[3];
    const float* gate   = (const float*)d_in[4];
    float* out = (float*)d_out;
    const int Nn = in_sizes[3];

    cudaFuncSetAttribute(gemm1_kernel, cudaFuncAttributeMaxDynamicSharedMemorySize, SM1_BYTES);
    cudaFuncSetAttribute(gemm2_kernel, cudaFuncAttributeMaxDynamicSharedMemorySize, SM2_BYTES);

    const int nbN = (Nn + 255) / 256;
    proj_kernel<<<B_DIM, 256>>>(state, W);
    patprep_kernel<<<(NPAD * D_DIM / 4) / 256, 256>>>(pat, Nn);   // also does init
    bias_kernel<<<nbN, 256>>>(depths, gate, Nn);

    gemm1_kernel<<<dim3(B_DIM / 128, NT1), 256, SM1_BYTES>>>(Nn);
    lse_merge_kernel<<<B_DIM / 256, 256>>>(NT1);

    const int CHv = ((Nn + NSPLIT * 64 - 1) / (NSPLIT * 64)) * 64;
    gemm2_kernel<<<dim3(B_DIM / 64, NSPLIT), 256, SM2_BYTES>>>(Nn, CHv);

    reduce_ret_kernel<<<(B_DIM * D_DIM / 4) / 256, 256>>>(out);
    depths_kernel<<<nbN, 256>>>(depths, out, Nn);
}